// round 4
// baseline (speedup 1.0000x reference)
#include <cuda_runtime.h>
#include <cuda_bf16.h>
#include <math.h>
#include <stdint.h>

// Problem constants
#define NB   4
#define SEQ  2048
#define DH   1024
#define NH   16
#define HD   64
#define MROWS (NB*SEQ)          // 8192

// ---------------- scratch (static device globals; no allocation) -------------
__device__ float g_xn[MROWS * DH];
__device__ float g_q [MROWS * DH];
__device__ float g_k [MROWS * DH];
__device__ float g_v [MROWS * DH];
__device__ float g_z [MROWS * DH];

// ---------------------------- helpers -----------------------------------------
__device__ __forceinline__ float f_tf32(float x) {
    uint32_t r;
    asm("cvt.rna.tf32.f32 %0, %1;" : "=r"(r) : "f"(x));
    return __uint_as_float(r);
}

__device__ __forceinline__ void mma_tf32(float* c, const float* a, const float* b) {
    asm volatile(
        "mma.sync.aligned.m16n8k8.row.col.f32.tf32.tf32.f32 "
        "{%0,%1,%2,%3}, {%4,%5,%6,%7}, {%8,%9}, {%0,%1,%2,%3};\n"
        : "+f"(c[0]), "+f"(c[1]), "+f"(c[2]), "+f"(c[3])
        : "r"(__float_as_uint(a[0])), "r"(__float_as_uint(a[1])),
          "r"(__float_as_uint(a[2])), "r"(__float_as_uint(a[3])),
          "r"(__float_as_uint(b[0])), "r"(__float_as_uint(b[1])));
}

// ---------------------------- LayerNorm --------------------------------------
__global__ __launch_bounds__(256) void ln_kernel(
    const float* __restrict__ x, const float* __restrict__ gamma,
    const float* __restrict__ beta, float* __restrict__ xn)
{
    __shared__ float red[256];
    int row = blockIdx.x;
    const float* xr = x + (size_t)row * DH;
    float* outr = xn + (size_t)row * DH;
    int t = threadIdx.x;

    float s = 0.f, sq = 0.f;
    #pragma unroll
    for (int i = 0; i < 4; i++) {
        float v = xr[t + i * 256];
        s += v; sq += v * v;
    }
    red[t] = s; __syncthreads();
    for (int off = 128; off > 0; off >>= 1) {
        if (t < off) red[t] += red[t + off];
        __syncthreads();
    }
    float mu = red[0] * (1.0f / DH);
    __syncthreads();
    red[t] = sq; __syncthreads();
    for (int off = 128; off > 0; off >>= 1) {
        if (t < off) red[t] += red[t + off];
        __syncthreads();
    }
    float var = red[0] * (1.0f / DH) - mu * mu;
    float inv = rsqrtf(var + 1e-5f);
    #pragma unroll
    for (int i = 0; i < 4; i++) {
        int c = t + i * 256;
        outr[c] = (xr[c] - mu) * inv * gamma[c] + beta[c];
    }
}

// ------------------- GEMM (tf32, pipelined): C = A @ W^T + bias ---------------
// Tile 128x128x32, 8 warps of 64x32. Double-buffered smem, register prefetch.
// Smem layout per row: grouped by (k mod 4): position p = (k&3)*8 + (k>>2).
#define SA 36       // row stride (32 data + 4 pad floats)
#define GTILE (128 * SA)

__global__ __launch_bounds__(256, 2) void gemm_tf32_kernel(
    const float* __restrict__ A, const float* __restrict__ W,
    const float* __restrict__ bias, float* __restrict__ C,
    int M, int N, int K)
{
    extern __shared__ float gsm[];
    float* As = gsm;                 // [2][128*SA]
    float* Bs = gsm + 2 * GTILE;     // [2][128*SA]

    int t    = threadIdx.x;
    int lane = t & 31;
    int wid  = t >> 5;
    int lr = lane >> 2;
    int lc = lane & 3;
    int m_base = (wid & 1) * 64;
    int n_base = (wid >> 1) * 32;
    int m0 = blockIdx.y * 128;
    int n0 = blockIdx.x * 128;

    // per-thread staging geometry: float4 f = t + i*256 -> row=(t>>3)+32i, j=t&7
    int srow = t >> 3;          // 0..31
    int sj   = t & 7;           // 0..7  (k4-group index)
    const float* Ag = A + (size_t)(m0 + srow) * K + sj * 4;
    const float* Wg = W + (size_t)(n0 + srow) * K + sj * 4;

    float acc[4][4][4];
    #pragma unroll
    for (int i = 0; i < 4; i++)
        #pragma unroll
        for (int j = 0; j < 4; j++)
            #pragma unroll
            for (int e = 0; e < 4; e++) acc[i][j][e] = 0.f;

    float4 pa[4], pb[4];
    // prologue: load tile 0
    #pragma unroll
    for (int i = 0; i < 4; i++) {
        pa[i] = *(const float4*)&Ag[(size_t)(32 * i) * K];
        pb[i] = *(const float4*)&Wg[(size_t)(32 * i) * K];
    }
    #pragma unroll
    for (int i = 0; i < 4; i++) {
        float* da = &As[(srow + 32 * i) * SA + sj];
        da[0] = f_tf32(pa[i].x); da[8]  = f_tf32(pa[i].y);
        da[16] = f_tf32(pa[i].z); da[24] = f_tf32(pa[i].w);
        float* db = &Bs[(srow + 32 * i) * SA + sj];
        db[0] = f_tf32(pb[i].x); db[8]  = f_tf32(pb[i].y);
        db[16] = f_tf32(pb[i].z); db[24] = f_tf32(pb[i].w);
    }
    __syncthreads();

    int buf = 0;
    for (int k0 = 0; k0 < K; k0 += 32) {
        bool more = (k0 + 32 < K);
        if (more) {
            #pragma unroll
            for (int i = 0; i < 4; i++) {
                pa[i] = *(const float4*)&Ag[(size_t)(32 * i) * K + k0 + 32];
                pb[i] = *(const float4*)&Wg[(size_t)(32 * i) * K + k0 + 32];
            }
        }

        const float* Ab = &As[buf * GTILE];
        const float* Bb = &Bs[buf * GTILE];
        #pragma unroll
        for (int kk = 0; kk < 4; kk++) {
            float a[4][4], b[4][2];
            #pragma unroll
            for (int mf = 0; mf < 4; mf++) {
                int row = m_base + mf * 16 + lr;
                float2 lo = *(const float2*)&Ab[row * SA + lc * 8 + 2 * kk];
                float2 hi = *(const float2*)&Ab[(row + 8) * SA + lc * 8 + 2 * kk];
                a[mf][0] = lo.x; a[mf][1] = hi.x; a[mf][2] = lo.y; a[mf][3] = hi.y;
            }
            #pragma unroll
            for (int nf = 0; nf < 4; nf++) {
                int col = n_base + nf * 8 + lr;
                float2 bb = *(const float2*)&Bb[col * SA + lc * 8 + 2 * kk];
                b[nf][0] = bb.x; b[nf][1] = bb.y;
            }
            #pragma unroll
            for (int mf = 0; mf < 4; mf++)
                #pragma unroll
                for (int nf = 0; nf < 4; nf++)
                    mma_tf32(acc[mf][nf], a[mf], b[nf]);
        }

        if (more) {
            float* Aw = &As[(buf ^ 1) * GTILE];
            float* Bw = &Bs[(buf ^ 1) * GTILE];
            #pragma unroll
            for (int i = 0; i < 4; i++) {
                float* da = &Aw[(srow + 32 * i) * SA + sj];
                da[0] = f_tf32(pa[i].x); da[8]  = f_tf32(pa[i].y);
                da[16] = f_tf32(pa[i].z); da[24] = f_tf32(pa[i].w);
                float* db = &Bw[(srow + 32 * i) * SA + sj];
                db[0] = f_tf32(pb[i].x); db[8]  = f_tf32(pb[i].y);
                db[16] = f_tf32(pb[i].z); db[24] = f_tf32(pb[i].w);
            }
        }
        __syncthreads();
        buf ^= 1;
    }

    // epilogue: bias + store
    #pragma unroll
    for (int nf = 0; nf < 4; nf++) {
        int col = n0 + n_base + nf * 8 + 2 * lc;
        float b0 = bias[col], b1 = bias[col + 1];
        #pragma unroll
        for (int mf = 0; mf < 4; mf++) {
            int row = m0 + m_base + mf * 16 + lr;
            *(float2*)&C[(size_t)row * N + col] =
                make_float2(acc[mf][nf][0] + b0, acc[mf][nf][1] + b1);
            *(float2*)&C[(size_t)(row + 8) * N + col] =
                make_float2(acc[mf][nf][2] + b0, acc[mf][nf][3] + b1);
        }
    }
}
#define GEMM_SMEM (4 * GTILE * (int)sizeof(float))

// ------------------- Flash Attention (tf32, grouped layouts) -------------------
// CTA per (n, h, 128-query tile); 8 warps x 16-row stripes; key tiles of 64.
// Grouped k layout (64 wide): p(k) = (k&3)*16 + (k>>2); row stride 68.
#define BQ  128
#define BKT 64
#define AST 68
#define ATTN_SMEM ((BQ*AST + BKT*AST + BKT*AST + BQ*AST) * (int)sizeof(float))

__global__ __launch_bounds__(256, 2) void attn_kernel(
    const float* __restrict__ q, const float* __restrict__ k,
    const float* __restrict__ v, float* __restrict__ z)
{
    extern __shared__ float sm[];
    float* Qs = sm;                    // [128 r][p(d)]  scaled, tf32
    float* Ks = Qs + BQ * AST;         // [64 y][p(d)]
    float* Vt = Ks + BKT * AST;        // [64 d][p(y)]   (transposed)
    float* Ps = Vt + BKT * AST;        // [128 r][p(y)]  per-warp stripes

    int xc = (gridDim.x - 1) - blockIdx.x;   // heavy tiles first
    int h  = blockIdx.y;
    int n  = blockIdx.z;
    int x0 = xc * BQ;
    int t    = threadIdx.x;
    int lane = t & 31;
    int wid  = t >> 5;
    int lr = lane >> 2;
    int lc = lane & 3;
    int m_base = wid * 16;
    float* Pw = Ps + m_base * AST;

    const float* qb = q + ((size_t)n * SEQ) * DH + h * HD;
    const float* kb = k + ((size_t)n * SEQ) * DH + h * HD;
    const float* vb = v + ((size_t)n * SEQ) * DH + h * HD;

    // stage Q: float4 loads, grouped scatter, scale folded in
    #pragma unroll
    for (int i = 0; i < 8; i++) {
        int f = t + i * 256;
        int r = f >> 4, c4 = (f & 15) * 4;
        float4 va = *(const float4*)&qb[(size_t)(x0 + r) * DH + c4];
        float* dst = &Qs[r * AST + (c4 >> 2)];
        dst[0]  = f_tf32(va.x * 0.125f);
        dst[16] = f_tf32(va.y * 0.125f);
        dst[32] = f_tf32(va.z * 0.125f);
        dst[48] = f_tf32(va.w * 0.125f);
    }

    float m_lo = -INFINITY, m_hi = -INFINITY, l_lo = 0.f, l_hi = 0.f;
    float o[8][4];
    #pragma unroll
    for (int nf = 0; nf < 8; nf++)
        #pragma unroll
        for (int e = 0; e < 4; e++) o[nf][e] = 0.f;

    int yend = x0 + BQ;
    for (int y0 = 0; y0 < yend; y0 += BKT) {
        __syncthreads();   // prior iter reads done; Qs visible on iter 0
        #pragma unroll
        for (int i = 0; i < 4; i++) {
            int f = t + i * 256;
            int y = f >> 4, c4 = (f & 15) * 4;
            float4 kv4 = *(const float4*)&kb[(size_t)(y0 + y) * DH + c4];
            float* kd = &Ks[y * AST + (c4 >> 2)];
            kd[0]  = f_tf32(kv4.x); kd[16] = f_tf32(kv4.y);
            kd[32] = f_tf32(kv4.z); kd[48] = f_tf32(kv4.w);
            float4 vv4 = *(const float4*)&vb[(size_t)(y0 + y) * DH + c4];
            int py = (y & 3) * 16 + (y >> 2);
            Vt[(c4 + 0) * AST + py] = f_tf32(vv4.x);
            Vt[(c4 + 1) * AST + py] = f_tf32(vv4.y);
            Vt[(c4 + 2) * AST + py] = f_tf32(vv4.z);
            Vt[(c4 + 3) * AST + py] = f_tf32(vv4.w);
        }
        __syncthreads();

        // ---- S = Q K^T : 16 x 64 per warp ----
        float s[8][4];
        #pragma unroll
        for (int nf = 0; nf < 8; nf++)
            #pragma unroll
            for (int e = 0; e < 4; e++) s[nf][e] = 0.f;

        #pragma unroll
        for (int kk = 0; kk < 8; kk++) {
            int rowa = m_base + lr;
            float2 qlo = *(const float2*)&Qs[rowa * AST + lc * 16 + 2 * kk];
            float2 qhi = *(const float2*)&Qs[(rowa + 8) * AST + lc * 16 + 2 * kk];
            float a[4] = {qlo.x, qhi.x, qlo.y, qhi.y};
            #pragma unroll
            for (int nf = 0; nf < 8; nf++) {
                int y = nf * 8 + lr;
                float2 b2 = *(const float2*)&Ks[y * AST + lc * 16 + 2 * kk];
                float b[2] = {b2.x, b2.y};
                mma_tf32(s[nf], a, b);
            }
        }

        // ---- causal mask (straddling tiles only) ----
        if (y0 + BKT - 1 > x0) {
            int r_lo = x0 + m_base + lr;
            #pragma unroll
            for (int nf = 0; nf < 8; nf++) {
                int c = y0 + nf * 8 + 2 * lc;
                if (c     > r_lo) s[nf][0] = -INFINITY;
                if (c + 1 > r_lo) s[nf][1] = -INFINITY;
                if (c     > r_lo + 8) s[nf][2] = -INFINITY;
                if (c + 1 > r_lo + 8) s[nf][3] = -INFINITY;
            }
        }

        // ---- online softmax (4-lane row groups) ----
        float mt_lo = -INFINITY, mt_hi = -INFINITY;
        #pragma unroll
        for (int nf = 0; nf < 8; nf++) {
            mt_lo = fmaxf(mt_lo, fmaxf(s[nf][0], s[nf][1]));
            mt_hi = fmaxf(mt_hi, fmaxf(s[nf][2], s[nf][3]));
        }
        #pragma unroll
        for (int off = 1; off <= 2; off <<= 1) {
            mt_lo = fmaxf(mt_lo, __shfl_xor_sync(0xffffffffu, mt_lo, off));
            mt_hi = fmaxf(mt_hi, __shfl_xor_sync(0xffffffffu, mt_hi, off));
        }
        float mn_lo = fmaxf(m_lo, mt_lo);
        float mn_hi = fmaxf(m_hi, mt_hi);
        float al_lo = __expf(m_lo - mn_lo);
        float al_hi = __expf(m_hi - mn_hi);
        m_lo = mn_lo; m_hi = mn_hi;

        float rs_lo = 0.f, rs_hi = 0.f;
        #pragma unroll
        for (int nf = 0; nf < 8; nf++) {
            s[nf][0] = __expf(s[nf][0] - mn_lo);
            s[nf][1] = __expf(s[nf][1] - mn_lo);
            s[nf][2] = __expf(s[nf][2] - mn_hi);
            s[nf][3] = __expf(s[nf][3] - mn_hi);
            rs_lo += s[nf][0] + s[nf][1];
            rs_hi += s[nf][2] + s[nf][3];
        }
        #pragma unroll
        for (int off = 1; off <= 2; off <<= 1) {
            rs_lo += __shfl_xor_sync(0xffffffffu, rs_lo, off);
            rs_hi += __shfl_xor_sync(0xffffffffu, rs_hi, off);
        }
        l_lo = l_lo * al_lo + rs_lo;
        l_hi = l_hi * al_hi + rs_hi;
        #pragma unroll
        for (int nf = 0; nf < 8; nf++) {
            o[nf][0] *= al_lo; o[nf][1] *= al_lo;
            o[nf][2] *= al_hi; o[nf][3] *= al_hi;
        }

        // ---- stage P (warp-private, grouped p(y)) ----
        #pragma unroll
        for (int nf = 0; nf < 8; nf++) {
            int p0 = ((2 * lc) & 3) * 16 + 2 * nf + (lc >> 1);
            int p1 = ((2 * lc + 1) & 3) * 16 + 2 * nf + (lc >> 1);
            Pw[lr * AST + p0]       = f_tf32(s[nf][0]);
            Pw[lr * AST + p1]       = f_tf32(s[nf][1]);
            Pw[(lr + 8) * AST + p0] = f_tf32(s[nf][2]);
            Pw[(lr + 8) * AST + p1] = f_tf32(s[nf][3]);
        }
        __syncwarp();

        // ---- O += P V : 16 x 64 per warp ----
        #pragma unroll
        for (int kk = 0; kk < 8; kk++) {
            float2 plo = *(const float2*)&Pw[lr * AST + lc * 16 + 2 * kk];
            float2 phi = *(const float2*)&Pw[(lr + 8) * AST + lc * 16 + 2 * kk];
            float a[4] = {plo.x, phi.x, plo.y, phi.y};
            #pragma unroll
            for (int nf = 0; nf < 8; nf++) {
                int d = nf * 8 + lr;
                float2 v2 = *(const float2*)&Vt[d * AST + lc * 16 + 2 * kk];
                float b[2] = {v2.x, v2.y};
                mma_tf32(o[nf], a, b);
            }
        }
        __syncwarp();
    }

    // ---- normalize + store ----
    float inv_lo = 1.0f / l_lo;
    float inv_hi = 1.0f / l_hi;
    int r_lo = x0 + m_base + lr;
    #pragma unroll
    for (int nf = 0; nf < 8; nf++) {
        int d = nf * 8 + 2 * lc;
        float* zlo = &z[((size_t)n * SEQ + r_lo) * DH + h * HD + d];
        float* zhi = &z[((size_t)n * SEQ + r_lo + 8) * DH + h * HD + d];
        *(float2*)zlo = make_float2(o[nf][0] * inv_lo, o[nf][1] * inv_lo);
        *(float2*)zhi = make_float2(o[nf][2] * inv_hi, o[nf][3] * inv_hi);
    }
}

// ------------------------------ launcher --------------------------------------
extern "C" void kernel_launch(void* const* d_in, const int* in_sizes, int n_in,
                              void* d_out, int out_size)
{
    const float* x     = (const float*)d_in[0];
    const float* Wq    = (const float*)d_in[1];
    const float* bq    = (const float*)d_in[2];
    const float* Wk    = (const float*)d_in[3];
    const float* bk    = (const float*)d_in[4];
    const float* Wv    = (const float*)d_in[5];
    const float* bv    = (const float*)d_in[6];
    const float* Wo    = (const float*)d_in[7];
    const float* bo    = (const float*)d_in[8];
    const float* gamma = (const float*)d_in[9];
    const float* beta  = (const float*)d_in[10];
    float* out = (float*)d_out;

    float *xn, *qp, *kp, *vp, *zp;
    cudaGetSymbolAddress((void**)&xn, g_xn);
    cudaGetSymbolAddress((void**)&qp, g_q);
    cudaGetSymbolAddress((void**)&kp, g_k);
    cudaGetSymbolAddress((void**)&vp, g_v);
    cudaGetSymbolAddress((void**)&zp, g_z);

    cudaFuncSetAttribute(gemm_tf32_kernel,
                         cudaFuncAttributeMaxDynamicSharedMemorySize, GEMM_SMEM);
    cudaFuncSetAttribute(attn_kernel,
                         cudaFuncAttributeMaxDynamicSharedMemorySize, ATTN_SMEM);

    // 1. LayerNorm
    ln_kernel<<<MROWS, 256>>>(x, gamma, beta, xn);

    // 2. Q/K/V projections
    dim3 ggrid(DH / 128, MROWS / 128);
    gemm_tf32_kernel<<<ggrid, 256, GEMM_SMEM>>>(xn, Wq, bq, qp, MROWS, DH, DH);
    gemm_tf32_kernel<<<ggrid, 256, GEMM_SMEM>>>(xn, Wk, bk, kp, MROWS, DH, DH);
    gemm_tf32_kernel<<<ggrid, 256, GEMM_SMEM>>>(xn, Wv, bv, vp, MROWS, DH, DH);

    // 3. causal multi-head attention
    dim3 agrid(SEQ / BQ, NH, NB);
    attn_kernel<<<agrid, 256, ATTN_SMEM>>>(qp, kp, vp, zp);

    // 4. output projection
    gemm_tf32_kernel<<<ggrid, 256, GEMM_SMEM>>>(zp, Wo, bo, out, MROWS, DH, DH);
}

// round 6
// speedup vs baseline: 1.4252x; 1.4252x over previous
#include <cuda_runtime.h>
#include <cuda_bf16.h>
#include <math.h>
#include <stdint.h>

// Problem constants
#define NB   4
#define SEQ  2048
#define DH   1024
#define NH   16
#define HD   64
#define MROWS (NB*SEQ)          // 8192

// GEMM dims are fixed for every call in this problem
#define GM MROWS
#define GN DH
#define GK DH

// ---------------- scratch (static device globals; no allocation) -------------
__device__ float g_xn[MROWS * DH];
__device__ float g_q [MROWS * DH];
__device__ float g_k [MROWS * DH];
__device__ float g_v [MROWS * DH];
__device__ float g_z [MROWS * DH];

// ---------------------------- helpers -----------------------------------------
__device__ __forceinline__ float f_tf32(float x) {
    uint32_t r;
    asm("cvt.rna.tf32.f32 %0, %1;" : "=r"(r) : "f"(x));
    return __uint_as_float(r);
}

__device__ __forceinline__ void mma_tf32(float* c, const float* a, const float* b) {
    asm volatile(
        "mma.sync.aligned.m16n8k8.row.col.f32.tf32.tf32.f32 "
        "{%0,%1,%2,%3}, {%4,%5,%6,%7}, {%8,%9}, {%0,%1,%2,%3};\n"
        : "+f"(c[0]), "+f"(c[1]), "+f"(c[2]), "+f"(c[3])
        : "r"(__float_as_uint(a[0])), "r"(__float_as_uint(a[1])),
          "r"(__float_as_uint(a[2])), "r"(__float_as_uint(a[3])),
          "r"(__float_as_uint(b[0])), "r"(__float_as_uint(b[1])));
}

// ---------------------------- LayerNorm --------------------------------------
__global__ __launch_bounds__(256) void ln_kernel(
    const float* __restrict__ x, const float* __restrict__ gamma,
    const float* __restrict__ beta, float* __restrict__ xn)
{
    __shared__ float2 red[256];
    int row = blockIdx.x;
    const float* xr = x + (size_t)row * DH;
    float* outr = xn + (size_t)row * DH;
    int t = threadIdx.x;

    float s = 0.f, sq = 0.f;
    #pragma unroll
    for (int i = 0; i < 4; i++) {
        float v = xr[t + i * 256];
        s += v; sq += v * v;
    }
    red[t] = make_float2(s, sq);
    __syncthreads();
    for (int off = 128; off > 0; off >>= 1) {
        if (t < off) {
            float2 a = red[t], b = red[t + off];
            red[t] = make_float2(a.x + b.x, a.y + b.y);
        }
        __syncthreads();
    }
    float mu  = red[0].x * (1.0f / DH);
    float var = red[0].y * (1.0f / DH) - mu * mu;
    float inv = rsqrtf(var + 1e-5f);
    #pragma unroll
    for (int i = 0; i < 4; i++) {
        int c = t + i * 256;
        outr[c] = (xr[c] - mu) * inv * gamma[c] + beta[c];
    }
}

// ------------------- GEMM (tf32 tensor cores): C = A @ W^T + bias -------------
// A: [GM,GK] row-major, W: [GN,GK] row-major. Tile 128x128x32, 8 warps of 64x32.
// Structure identical to round-3 (verified 147us); dims compile-time.
#define BKG 32
#define SA  36

__global__ __launch_bounds__(256, 2) void gemm_tf32_kernel(
    const float* __restrict__ A, const float* __restrict__ W,
    const float* __restrict__ bias, float* __restrict__ C)
{
    __shared__ float As[128 * SA];
    __shared__ float Bs[128 * SA];

    int t    = threadIdx.x;
    int lane = t & 31;
    int wid  = t >> 5;
    int lr = lane >> 2;     // 0..7
    int lc = lane & 3;      // 0..3
    int m_base = (wid & 1) * 64;
    int n_base = (wid >> 1) * 32;
    int m0 = blockIdx.y * 128;
    int n0 = blockIdx.x * 128;

    float acc[4][4][4];
    #pragma unroll
    for (int i = 0; i < 4; i++)
        #pragma unroll
        for (int j = 0; j < 4; j++)
            #pragma unroll
            for (int e = 0; e < 4; e++) acc[i][j][e] = 0.f;

    for (int k0 = 0; k0 < GK; k0 += BKG) {
        // stage tiles (convert to tf32 on the way in)
        #pragma unroll
        for (int i = 0; i < 4; i++) {
            int e   = t + i * 256;
            int row = e >> 3;
            int c4  = (e & 7) * 4;
            float4 va = *(const float4*)&A[(size_t)(m0 + row) * GK + k0 + c4];
            As[row * SA + c4 + 0] = f_tf32(va.x);
            As[row * SA + c4 + 1] = f_tf32(va.y);
            As[row * SA + c4 + 2] = f_tf32(va.z);
            As[row * SA + c4 + 3] = f_tf32(va.w);
            float4 vb = *(const float4*)&W[(size_t)(n0 + row) * GK + k0 + c4];
            Bs[row * SA + c4 + 0] = f_tf32(vb.x);
            Bs[row * SA + c4 + 1] = f_tf32(vb.y);
            Bs[row * SA + c4 + 2] = f_tf32(vb.z);
            Bs[row * SA + c4 + 3] = f_tf32(vb.w);
        }
        __syncthreads();

        #pragma unroll
        for (int kk = 0; kk < BKG / 8; kk++) {
            int kb = kk * 8;
            float a[4][4], b[4][2];
            #pragma unroll
            for (int mf = 0; mf < 4; mf++) {
                int row = m_base + mf * 16 + lr;
                a[mf][0] = As[row * SA + kb + lc];
                a[mf][1] = As[(row + 8) * SA + kb + lc];
                a[mf][2] = As[row * SA + kb + 4 + lc];
                a[mf][3] = As[(row + 8) * SA + kb + 4 + lc];
            }
            #pragma unroll
            for (int nf = 0; nf < 4; nf++) {
                int col = n_base + nf * 8 + lr;
                b[nf][0] = Bs[col * SA + kb + lc];
                b[nf][1] = Bs[col * SA + kb + 4 + lc];
            }
            #pragma unroll
            for (int mf = 0; mf < 4; mf++)
                #pragma unroll
                for (int nf = 0; nf < 4; nf++)
                    mma_tf32(acc[mf][nf], a[mf], b[nf]);
        }
        __syncthreads();
    }

    // epilogue: bias + store
    #pragma unroll
    for (int nf = 0; nf < 4; nf++) {
        int col = n0 + n_base + nf * 8 + 2 * lc;
        float b0 = bias[col], b1 = bias[col + 1];
        #pragma unroll
        for (int mf = 0; mf < 4; mf++) {
            int row = m0 + m_base + mf * 16 + lr;
            *(float2*)&C[(size_t)row * GN + col] =
                make_float2(acc[mf][nf][0] + b0, acc[mf][nf][1] + b1);
            *(float2*)&C[(size_t)(row + 8) * GN + col] =
                make_float2(acc[mf][nf][2] + b0, acc[mf][nf][3] + b1);
        }
    }
}

// ------------------- Flash Attention (tf32 tensor cores) -----------------------
// Round-3 structure; only change: 2 CTAs/SM (2 x 104KB smem fits 228KB).
#define BQ  128
#define BKT 64
#define AST 68     // smem row stride (floats)
#define ATTN_SMEM ((BQ*AST + BKT*AST + BKT*AST + BQ*AST) * (int)sizeof(float))

__global__ __launch_bounds__(256, 2) void attn_kernel(
    const float* __restrict__ q, const float* __restrict__ k,
    const float* __restrict__ v, float* __restrict__ z)
{
    extern __shared__ float sm[];
    float* Qs = sm;                    // [128 r][AST] row-major, tf32, scaled
    float* Ks = Qs + BQ * AST;         // [64 y][AST]
    float* Vs = Ks + BKT * AST;        // [64 y][AST]
    float* Ps = Vs + BKT * AST;        // [128 r][AST]  (per-warp private stripes)

    int xc = (gridDim.x - 1) - blockIdx.x;   // heavy tiles first
    int h  = blockIdx.y;
    int n  = blockIdx.z;
    int x0 = xc * BQ;
    int t    = threadIdx.x;
    int lane = t & 31;
    int wid  = t >> 5;
    int lr = lane >> 2;
    int lc = lane & 3;
    int m_base = wid * 16;             // warp's query-row stripe
    float* Pw = Ps + m_base * AST;     // warp-private P staging

    const float* qb = q + ((size_t)n * SEQ) * DH + h * HD;
    const float* kb = k + ((size_t)n * SEQ) * DH + h * HD;
    const float* vb = v + ((size_t)n * SEQ) * DH + h * HD;

    // stage Q (scaled by 1/8, tf32-rounded)
    for (int idx = t; idx < BQ * HD; idx += 256) {
        int r = idx >> 6, d = idx & 63;
        Qs[r * AST + d] = f_tf32(qb[(size_t)(x0 + r) * DH + d] * 0.125f);
    }

    // per-thread state: rows r_lo = m_base+lr, r_hi = +8
    float m_lo = -INFINITY, m_hi = -INFINITY, l_lo = 0.f, l_hi = 0.f;
    float o[8][4];
    #pragma unroll
    for (int nf = 0; nf < 8; nf++)
        #pragma unroll
        for (int e = 0; e < 4; e++) o[nf][e] = 0.f;

    int yend = x0 + BQ;
    for (int y0 = 0; y0 < yend; y0 += BKT) {
        __syncthreads();   // prior iter's reads of Ks/Vs done; Qs visible (iter 0)
        for (int idx = t; idx < BKT * HD; idx += 256) {
            int y = idx >> 6, d = idx & 63;
            Ks[y * AST + d] = f_tf32(kb[(size_t)(y0 + y) * DH + d]);
            Vs[y * AST + d] = f_tf32(vb[(size_t)(y0 + y) * DH + d]);
        }
        __syncthreads();

        // ---- S = Q K^T : warp computes 16 x 64 ----
        float s[8][4];
        #pragma unroll
        for (int nf = 0; nf < 8; nf++)
            #pragma unroll
            for (int e = 0; e < 4; e++) s[nf][e] = 0.f;

        #pragma unroll
        for (int kk = 0; kk < 8; kk++) {
            int kb8 = kk * 8;
            float a[4];
            int row = m_base + lr;
            a[0] = Qs[row * AST + kb8 + lc];
            a[1] = Qs[(row + 8) * AST + kb8 + lc];
            a[2] = Qs[row * AST + kb8 + 4 + lc];
            a[3] = Qs[(row + 8) * AST + kb8 + 4 + lc];
            #pragma unroll
            for (int nf = 0; nf < 8; nf++) {
                float b[2];
                int y = nf * 8 + lr;
                b[0] = Ks[y * AST + kb8 + lc];
                b[1] = Ks[y * AST + kb8 + 4 + lc];
                mma_tf32(s[nf], a, b);
            }
        }

        // ---- causal mask (only straddling tiles) ----
        if (y0 + BKT - 1 > x0) {
            int r_lo = x0 + m_base + lr;
            #pragma unroll
            for (int nf = 0; nf < 8; nf++) {
                int c = y0 + nf * 8 + 2 * lc;
                if (c     > r_lo) s[nf][0] = -INFINITY;
                if (c + 1 > r_lo) s[nf][1] = -INFINITY;
                if (c     > r_lo + 8) s[nf][2] = -INFINITY;
                if (c + 1 > r_lo + 8) s[nf][3] = -INFINITY;
            }
        }

        // ---- online softmax (row groups of 4 lanes) ----
        float mt_lo = -INFINITY, mt_hi = -INFINITY;
        #pragma unroll
        for (int nf = 0; nf < 8; nf++) {
            mt_lo = fmaxf(mt_lo, fmaxf(s[nf][0], s[nf][1]));
            mt_hi = fmaxf(mt_hi, fmaxf(s[nf][2], s[nf][3]));
        }
        #pragma unroll
        for (int off = 1; off <= 2; off <<= 1) {
            mt_lo = fmaxf(mt_lo, __shfl_xor_sync(0xffffffffu, mt_lo, off));
            mt_hi = fmaxf(mt_hi, __shfl_xor_sync(0xffffffffu, mt_hi, off));
        }
        float mn_lo = fmaxf(m_lo, mt_lo);
        float mn_hi = fmaxf(m_hi, mt_hi);
        float al_lo = __expf(m_lo - mn_lo);
        float al_hi = __expf(m_hi - mn_hi);
        m_lo = mn_lo; m_hi = mn_hi;

        float rs_lo = 0.f, rs_hi = 0.f;
        #pragma unroll
        for (int nf = 0; nf < 8; nf++) {
            s[nf][0] = __expf(s[nf][0] - mn_lo);
            s[nf][1] = __expf(s[nf][1] - mn_lo);
            s[nf][2] = __expf(s[nf][2] - mn_hi);
            s[nf][3] = __expf(s[nf][3] - mn_hi);
            rs_lo += s[nf][0] + s[nf][1];
            rs_hi += s[nf][2] + s[nf][3];
        }
        #pragma unroll
        for (int off = 1; off <= 2; off <<= 1) {
            rs_lo += __shfl_xor_sync(0xffffffffu, rs_lo, off);
            rs_hi += __shfl_xor_sync(0xffffffffu, rs_hi, off);
        }
        l_lo = l_lo * al_lo + rs_lo;
        l_hi = l_hi * al_hi + rs_hi;
        #pragma unroll
        for (int nf = 0; nf < 8; nf++) {
            o[nf][0] *= al_lo; o[nf][1] *= al_lo;
            o[nf][2] *= al_hi; o[nf][3] *= al_hi;
        }

        // ---- stage P (warp-private stripe; tf32-rounded) ----
        #pragma unroll
        for (int nf = 0; nf < 8; nf++) {
            int c = nf * 8 + 2 * lc;
            *(float2*)&Pw[lr * AST + c]       =
                make_float2(f_tf32(s[nf][0]), f_tf32(s[nf][1]));
            *(float2*)&Pw[(lr + 8) * AST + c] =
                make_float2(f_tf32(s[nf][2]), f_tf32(s[nf][3]));
        }
        __syncwarp();

        // ---- O += P V : warp computes 16 x 64 ----
        #pragma unroll
        for (int kk = 0; kk < 8; kk++) {
            int kb8 = kk * 8;
            float a[4];
            a[0] = Pw[lr * AST + kb8 + lc];
            a[1] = Pw[(lr + 8) * AST + kb8 + lc];
            a[2] = Pw[lr * AST + kb8 + 4 + lc];
            a[3] = Pw[(lr + 8) * AST + kb8 + 4 + lc];
            #pragma unroll
            for (int nf = 0; nf < 8; nf++) {
                float b[2];
                int d = nf * 8 + lr;
                b[0] = Vs[(kb8 + lc) * AST + d];
                b[1] = Vs[(kb8 + 4 + lc) * AST + d];
                mma_tf32(o[nf], a, b);
            }
        }
        __syncwarp();   // Pw reads done before next iter's overwrite
    }

    // ---- normalize + store ----
    float inv_lo = 1.0f / l_lo;
    float inv_hi = 1.0f / l_hi;
    int r_lo = x0 + m_base + lr;
    #pragma unroll
    for (int nf = 0; nf < 8; nf++) {
        int d = nf * 8 + 2 * lc;
        float* zlo = &z[((size_t)n * SEQ + r_lo) * DH + h * HD + d];
        float* zhi = &z[((size_t)n * SEQ + r_lo + 8) * DH + h * HD + d];
        *(float2*)zlo = make_float2(o[nf][0] * inv_lo, o[nf][1] * inv_lo);
        *(float2*)zhi = make_float2(o[nf][2] * inv_hi, o[nf][3] * inv_hi);
    }
}

// ------------------------------ launcher --------------------------------------
extern "C" void kernel_launch(void* const* d_in, const int* in_sizes, int n_in,
                              void* d_out, int out_size)
{
    const float* x     = (const float*)d_in[0];
    const float* Wq    = (const float*)d_in[1];
    const float* bq    = (const float*)d_in[2];
    const float* Wk    = (const float*)d_in[3];
    const float* bk    = (const float*)d_in[4];
    const float* Wv    = (const float*)d_in[5];
    const float* bv    = (const float*)d_in[6];
    const float* Wo    = (const float*)d_in[7];
    const float* bo    = (const float*)d_in[8];
    const float* gamma = (const float*)d_in[9];
    const float* beta  = (const float*)d_in[10];
    float* out = (float*)d_out;

    float *xn, *qp, *kp, *vp, *zp;
    cudaGetSymbolAddress((void**)&xn, g_xn);
    cudaGetSymbolAddress((void**)&qp, g_q);
    cudaGetSymbolAddress((void**)&kp, g_k);
    cudaGetSymbolAddress((void**)&vp, g_v);
    cudaGetSymbolAddress((void**)&zp, g_z);

    cudaFuncSetAttribute(attn_kernel,
                         cudaFuncAttributeMaxDynamicSharedMemorySize, ATTN_SMEM);

    // 1. LayerNorm
    ln_kernel<<<MROWS, 256>>>(x, gamma, beta, xn);

    // 2. Q/K/V projections (tf32 tensor cores)
    dim3 ggrid(GN / 128, GM / 128);
    gemm_tf32_kernel<<<ggrid, 256>>>(xn, Wq, bq, qp);
    gemm_tf32_kernel<<<ggrid, 256>>>(xn, Wk, bk, kp);
    gemm_tf32_kernel<<<ggrid, 256>>>(xn, Wv, bv, vp);

    // 3. causal multi-head attention (flash, tf32 tensor cores)
    dim3 agrid(SEQ / BQ, NH, NB);
    attn_kernel<<<agrid, 256, ATTN_SMEM>>>(qp, kp, vp, zp);

    // 4. output projection
    gemm_tf32_kernel<<<ggrid, 256>>>(zp, Wo, bo, out);
}

// round 7
// speedup vs baseline: 1.6479x; 1.1562x over previous
#include <cuda_runtime.h>
#include <cuda_bf16.h>
#include <math.h>
#include <stdint.h>

// Problem constants
#define NB   4
#define SEQ  2048
#define DH   1024
#define NH   16
#define HD   64
#define MROWS (NB*SEQ)          // 8192

#define GM MROWS
#define GN DH
#define GK DH

// ---------------- scratch (static device globals; no allocation) -------------
__device__ float g_xn[MROWS * DH];
__device__ float g_q [MROWS * DH];
__device__ float g_k [MROWS * DH];
__device__ float g_v [MROWS * DH];
__device__ float g_z [MROWS * DH];
__device__ float g_wt[4][DH * DH];     // tf32-rounded weights

// ---------------------------- helpers -----------------------------------------
__device__ __forceinline__ float f_tf32(float x) {
    uint32_t r;
    asm("cvt.rna.tf32.f32 %0, %1;" : "=r"(r) : "f"(x));
    return __uint_as_float(r);
}

__device__ __forceinline__ void mma_tf32(float* c, const float* a, const float* b) {
    asm volatile(
        "mma.sync.aligned.m16n8k8.row.col.f32.tf32.tf32.f32 "
        "{%0,%1,%2,%3}, {%4,%5,%6,%7}, {%8,%9}, {%0,%1,%2,%3};\n"
        : "+f"(c[0]), "+f"(c[1]), "+f"(c[2]), "+f"(c[3])
        : "r"(__float_as_uint(a[0])), "r"(__float_as_uint(a[1])),
          "r"(__float_as_uint(a[2])), "r"(__float_as_uint(a[3])),
          "r"(__float_as_uint(b[0])), "r"(__float_as_uint(b[1])));
}

__device__ __forceinline__ void cp_async16(void* smem, const void* gmem) {
    uint32_t s = (uint32_t)__cvta_generic_to_shared(smem);
    asm volatile("cp.async.cg.shared.global [%0], [%1], 16;" :: "r"(s), "l"(gmem));
}
__device__ __forceinline__ void cp_commit() {
    asm volatile("cp.async.commit_group;");
}
template<int N>
__device__ __forceinline__ void cp_wait() {
    asm volatile("cp.async.wait_group %0;" :: "n"(N));
}

// ----------------------- weight pre-round (tf32) ------------------------------
__global__ __launch_bounds__(256) void wcvt_kernel(
    const float* __restrict__ src, float* __restrict__ dst)
{
    int i = (blockIdx.x * 256 + threadIdx.x) * 4;
    float4 v = *(const float4*)&src[i];
    float4 o = make_float4(f_tf32(v.x), f_tf32(v.y), f_tf32(v.z), f_tf32(v.w));
    *(float4*)&dst[i] = o;
}

// ---------------------------- LayerNorm (tf32 out) ----------------------------
__global__ __launch_bounds__(256) void ln_kernel(
    const float* __restrict__ x, const float* __restrict__ gamma,
    const float* __restrict__ beta, float* __restrict__ xn)
{
    __shared__ float2 red[256];
    int row = blockIdx.x;
    const float* xr = x + (size_t)row * DH;
    float* outr = xn + (size_t)row * DH;
    int t = threadIdx.x;

    float s = 0.f, sq = 0.f;
    #pragma unroll
    for (int i = 0; i < 4; i++) {
        float v = xr[t + i * 256];
        s += v; sq += v * v;
    }
    red[t] = make_float2(s, sq);
    __syncthreads();
    for (int off = 128; off > 0; off >>= 1) {
        if (t < off) {
            float2 a = red[t], b = red[t + off];
            red[t] = make_float2(a.x + b.x, a.y + b.y);
        }
        __syncthreads();
    }
    float mu  = red[0].x * (1.0f / DH);
    float var = red[0].y * (1.0f / DH) - mu * mu;
    float inv = rsqrtf(var + 1e-5f);
    #pragma unroll
    for (int i = 0; i < 4; i++) {
        int c = t + i * 256;
        outr[c] = f_tf32((xr[c] - mu) * inv * gamma[c] + beta[c]);
    }
}

// ----------- GEMM (tf32, cp.async 2-stage pipeline): C = A @ W^T + bias -------
// Inputs MUST be tf32-rounded in gmem. Tile 128x128x32, 8 warps of 64x32.
#define SA 36
#define GTILE (128 * SA)
#define GEMM_SMEM (4 * GTILE * (int)sizeof(float))

template<bool ROUND_OUT>
__global__ __launch_bounds__(256, 2) void gemm_cp_kernel(
    const float* __restrict__ A, const float* __restrict__ W,
    const float* __restrict__ bias, float* __restrict__ C)
{
    extern __shared__ float gsm[];
    float* As = gsm;                 // [2][GTILE]
    float* Bs = gsm + 2 * GTILE;     // [2][GTILE]

    int t    = threadIdx.x;
    int lane = t & 31;
    int wid  = t >> 5;
    int lr = lane >> 2;
    int lc = lane & 3;
    int m_base = (wid & 1) * 64;
    int n_base = (wid >> 1) * 32;
    int m0 = blockIdx.y * 128;
    int n0 = blockIdx.x * 128;

    float acc[4][4][4];
    #pragma unroll
    for (int i = 0; i < 4; i++)
        #pragma unroll
        for (int j = 0; j < 4; j++)
            #pragma unroll
            for (int e = 0; e < 4; e++) acc[i][j][e] = 0.f;

    // staging map: e = t + i*256 -> row = e>>3 (0..127), c4 = (e&7)*4
    // prologue: tile 0 into buf 0
    #pragma unroll
    for (int i = 0; i < 4; i++) {
        int e = t + i * 256;
        int row = e >> 3, c4 = (e & 7) * 4;
        cp_async16(&As[row * SA + c4], &A[(size_t)(m0 + row) * GK + c4]);
        cp_async16(&Bs[row * SA + c4], &W[(size_t)(n0 + row) * GK + c4]);
    }
    cp_commit();

    int buf = 0;
    for (int k0 = 0; k0 < GK; k0 += 32) {
        bool more = (k0 + 32 < GK);
        if (more) {
            float* Aw = &As[(buf ^ 1) * GTILE];
            float* Bw = &Bs[(buf ^ 1) * GTILE];
            #pragma unroll
            for (int i = 0; i < 4; i++) {
                int e = t + i * 256;
                int row = e >> 3, c4 = (e & 7) * 4;
                cp_async16(&Aw[row * SA + c4],
                           &A[(size_t)(m0 + row) * GK + k0 + 32 + c4]);
                cp_async16(&Bw[row * SA + c4],
                           &W[(size_t)(n0 + row) * GK + k0 + 32 + c4]);
            }
            cp_commit();
            cp_wait<1>();
        } else {
            cp_wait<0>();
        }
        __syncthreads();

        const float* Ab = &As[buf * GTILE];
        const float* Bb = &Bs[buf * GTILE];
        #pragma unroll
        for (int kk = 0; kk < 4; kk++) {
            int kb = kk * 8;
            float a[4][4], b[4][2];
            #pragma unroll
            for (int mf = 0; mf < 4; mf++) {
                int row = m_base + mf * 16 + lr;
                a[mf][0] = Ab[row * SA + kb + lc];
                a[mf][1] = Ab[(row + 8) * SA + kb + lc];
                a[mf][2] = Ab[row * SA + kb + 4 + lc];
                a[mf][3] = Ab[(row + 8) * SA + kb + 4 + lc];
            }
            #pragma unroll
            for (int nf = 0; nf < 4; nf++) {
                int col = n_base + nf * 8 + lr;
                b[nf][0] = Bb[col * SA + kb + lc];
                b[nf][1] = Bb[col * SA + kb + 4 + lc];
            }
            #pragma unroll
            for (int mf = 0; mf < 4; mf++)
                #pragma unroll
                for (int nf = 0; nf < 4; nf++)
                    mma_tf32(acc[mf][nf], a[mf], b[nf]);
        }
        __syncthreads();   // all reads of buf done before it is refilled
        buf ^= 1;
    }

    // epilogue: bias + (optional tf32 round) + store
    #pragma unroll
    for (int nf = 0; nf < 4; nf++) {
        int col = n0 + n_base + nf * 8 + 2 * lc;
        float b0 = bias[col], b1 = bias[col + 1];
        #pragma unroll
        for (int mf = 0; mf < 4; mf++) {
            int row = m0 + m_base + mf * 16 + lr;
            float v0 = acc[mf][nf][0] + b0, v1 = acc[mf][nf][1] + b1;
            float v2 = acc[mf][nf][2] + b0, v3 = acc[mf][nf][3] + b1;
            if (ROUND_OUT) {
                v0 = f_tf32(v0); v1 = f_tf32(v1);
                v2 = f_tf32(v2); v3 = f_tf32(v3);
            }
            *(float2*)&C[(size_t)row * GN + col]       = make_float2(v0, v1);
            *(float2*)&C[(size_t)(row + 8) * GN + col] = make_float2(v2, v3);
        }
    }
}

// ------------------- Flash Attention (tf32, cp.async staging) ------------------
// Inputs q/k/v are tf32-rounded. Scale 1/8 applied post-mma (exact pow2).
#define BQ  128
#define BKT 64
#define AST 68
#define ATTN_SMEM ((BQ*AST + BKT*AST + BKT*AST + BQ*AST) * (int)sizeof(float))

__global__ __launch_bounds__(256, 2) void attn_kernel(
    const float* __restrict__ q, const float* __restrict__ k,
    const float* __restrict__ v, float* __restrict__ z)
{
    extern __shared__ float sm[];
    float* Qs = sm;                    // [128 r][AST]
    float* Ks = Qs + BQ * AST;         // [64 y][AST]
    float* Vs = Ks + BKT * AST;        // [64 y][AST]
    float* Ps = Vs + BKT * AST;        // [128 r][AST] per-warp stripes

    int xc = (gridDim.x - 1) - blockIdx.x;   // heavy tiles first
    int h  = blockIdx.y;
    int n  = blockIdx.z;
    int x0 = xc * BQ;
    int t    = threadIdx.x;
    int lane = t & 31;
    int wid  = t >> 5;
    int lr = lane >> 2;
    int lc = lane & 3;
    int m_base = wid * 16;
    float* Pw = Ps + m_base * AST;

    const float* qb = q + ((size_t)n * SEQ) * DH + h * HD;
    const float* kb = k + ((size_t)n * SEQ) * DH + h * HD;
    const float* vb = v + ((size_t)n * SEQ) * DH + h * HD;

    // stage Q via cp.async (8 float4/thread)
    #pragma unroll
    for (int i = 0; i < 8; i++) {
        int f = t + i * 256;
        int r = f >> 4, c4 = (f & 15) * 4;
        cp_async16(&Qs[r * AST + c4], &qb[(size_t)(x0 + r) * DH + c4]);
    }
    cp_commit();

    float m_lo = -INFINITY, m_hi = -INFINITY, l_lo = 0.f, l_hi = 0.f;
    float o[8][4];
    #pragma unroll
    for (int nf = 0; nf < 8; nf++)
        #pragma unroll
        for (int e = 0; e < 4; e++) o[nf][e] = 0.f;

    int yend = x0 + BQ;
    for (int y0 = 0; y0 < yend; y0 += BKT) {
        __syncthreads();   // prior iter reads of Ks/Vs done
        // stage K/V via cp.async (4 float4/thread each)
        #pragma unroll
        for (int i = 0; i < 4; i++) {
            int f = t + i * 256;
            int y = f >> 4, c4 = (f & 15) * 4;
            cp_async16(&Ks[y * AST + c4], &kb[(size_t)(y0 + y) * DH + c4]);
            cp_async16(&Vs[y * AST + c4], &vb[(size_t)(y0 + y) * DH + c4]);
        }
        cp_commit();
        cp_wait<0>();
        __syncthreads();

        // ---- S = Q K^T : warp computes 16 x 64 ----
        float s[8][4];
        #pragma unroll
        for (int nf = 0; nf < 8; nf++)
            #pragma unroll
            for (int e = 0; e < 4; e++) s[nf][e] = 0.f;

        #pragma unroll
        for (int kk = 0; kk < 8; kk++) {
            int kb8 = kk * 8;
            float a[4];
            int row = m_base + lr;
            a[0] = Qs[row * AST + kb8 + lc];
            a[1] = Qs[(row + 8) * AST + kb8 + lc];
            a[2] = Qs[row * AST + kb8 + 4 + lc];
            a[3] = Qs[(row + 8) * AST + kb8 + 4 + lc];
            #pragma unroll
            for (int nf = 0; nf < 8; nf++) {
                float b[2];
                int y = nf * 8 + lr;
                b[0] = Ks[y * AST + kb8 + lc];
                b[1] = Ks[y * AST + kb8 + 4 + lc];
                mma_tf32(s[nf], a, b);
            }
        }

        // scale (exact pow2, commutes with pre-scaling Q)
        #pragma unroll
        for (int nf = 0; nf < 8; nf++) {
            s[nf][0] *= 0.125f; s[nf][1] *= 0.125f;
            s[nf][2] *= 0.125f; s[nf][3] *= 0.125f;
        }

        // ---- causal mask (only straddling tiles) ----
        if (y0 + BKT - 1 > x0) {
            int r_lo = x0 + m_base + lr;
            #pragma unroll
            for (int nf = 0; nf < 8; nf++) {
                int c = y0 + nf * 8 + 2 * lc;
                if (c     > r_lo) s[nf][0] = -INFINITY;
                if (c + 1 > r_lo) s[nf][1] = -INFINITY;
                if (c     > r_lo + 8) s[nf][2] = -INFINITY;
                if (c + 1 > r_lo + 8) s[nf][3] = -INFINITY;
            }
        }

        // ---- online softmax (4-lane row groups) ----
        float mt_lo = -INFINITY, mt_hi = -INFINITY;
        #pragma unroll
        for (int nf = 0; nf < 8; nf++) {
            mt_lo = fmaxf(mt_lo, fmaxf(s[nf][0], s[nf][1]));
            mt_hi = fmaxf(mt_hi, fmaxf(s[nf][2], s[nf][3]));
        }
        #pragma unroll
        for (int off = 1; off <= 2; off <<= 1) {
            mt_lo = fmaxf(mt_lo, __shfl_xor_sync(0xffffffffu, mt_lo, off));
            mt_hi = fmaxf(mt_hi, __shfl_xor_sync(0xffffffffu, mt_hi, off));
        }
        float mn_lo = fmaxf(m_lo, mt_lo);
        float mn_hi = fmaxf(m_hi, mt_hi);
        float al_lo = __expf(m_lo - mn_lo);
        float al_hi = __expf(m_hi - mn_hi);
        m_lo = mn_lo; m_hi = mn_hi;

        float rs_lo = 0.f, rs_hi = 0.f;
        #pragma unroll
        for (int nf = 0; nf < 8; nf++) {
            s[nf][0] = __expf(s[nf][0] - mn_lo);
            s[nf][1] = __expf(s[nf][1] - mn_lo);
            s[nf][2] = __expf(s[nf][2] - mn_hi);
            s[nf][3] = __expf(s[nf][3] - mn_hi);
            rs_lo += s[nf][0] + s[nf][1];
            rs_hi += s[nf][2] + s[nf][3];
        }
        #pragma unroll
        for (int off = 1; off <= 2; off <<= 1) {
            rs_lo += __shfl_xor_sync(0xffffffffu, rs_lo, off);
            rs_hi += __shfl_xor_sync(0xffffffffu, rs_hi, off);
        }
        l_lo = l_lo * al_lo + rs_lo;
        l_hi = l_hi * al_hi + rs_hi;
        #pragma unroll
        for (int nf = 0; nf < 8; nf++) {
            o[nf][0] *= al_lo; o[nf][1] *= al_lo;
            o[nf][2] *= al_hi; o[nf][3] *= al_hi;
        }

        // ---- stage P (warp-private stripe; tf32-rounded) ----
        #pragma unroll
        for (int nf = 0; nf < 8; nf++) {
            int c = nf * 8 + 2 * lc;
            *(float2*)&Pw[lr * AST + c]       =
                make_float2(f_tf32(s[nf][0]), f_tf32(s[nf][1]));
            *(float2*)&Pw[(lr + 8) * AST + c] =
                make_float2(f_tf32(s[nf][2]), f_tf32(s[nf][3]));
        }
        __syncwarp();

        // ---- O += P V : warp computes 16 x 64 ----
        #pragma unroll
        for (int kk = 0; kk < 8; kk++) {
            int kb8 = kk * 8;
            float a[4];
            a[0] = Pw[lr * AST + kb8 + lc];
            a[1] = Pw[(lr + 8) * AST + kb8 + lc];
            a[2] = Pw[lr * AST + kb8 + 4 + lc];
            a[3] = Pw[(lr + 8) * AST + kb8 + 4 + lc];
            #pragma unroll
            for (int nf = 0; nf < 8; nf++) {
                float b[2];
                int d = nf * 8 + lr;
                b[0] = Vs[(kb8 + lc) * AST + d];
                b[1] = Vs[(kb8 + 4 + lc) * AST + d];
                mma_tf32(o[nf], a, b);
            }
        }
        __syncwarp();
    }

    // ---- normalize + store (tf32-rounded: feeds final GEMM) ----
    float inv_lo = 1.0f / l_lo;
    float inv_hi = 1.0f / l_hi;
    int r_lo = x0 + m_base + lr;
    #pragma unroll
    for (int nf = 0; nf < 8; nf++) {
        int d = nf * 8 + 2 * lc;
        float* zlo = &z[((size_t)n * SEQ + r_lo) * DH + h * HD + d];
        float* zhi = &z[((size_t)n * SEQ + r_lo + 8) * DH + h * HD + d];
        *(float2*)zlo = make_float2(f_tf32(o[nf][0] * inv_lo),
                                    f_tf32(o[nf][1] * inv_lo));
        *(float2*)zhi = make_float2(f_tf32(o[nf][2] * inv_hi),
                                    f_tf32(o[nf][3] * inv_hi));
    }
}

// ------------------------------ launcher --------------------------------------
extern "C" void kernel_launch(void* const* d_in, const int* in_sizes, int n_in,
                              void* d_out, int out_size)
{
    const float* x     = (const float*)d_in[0];
    const float* Wq    = (const float*)d_in[1];
    const float* bq    = (const float*)d_in[2];
    const float* Wk    = (const float*)d_in[3];
    const float* bk    = (const float*)d_in[4];
    const float* Wv    = (const float*)d_in[5];
    const float* bv    = (const float*)d_in[6];
    const float* Wo    = (const float*)d_in[7];
    const float* bo    = (const float*)d_in[8];
    const float* gamma = (const float*)d_in[9];
    const float* beta  = (const float*)d_in[10];
    float* out = (float*)d_out;

    float *xn, *qp, *kp, *vp, *zp, *wt;
    cudaGetSymbolAddress((void**)&xn, g_xn);
    cudaGetSymbolAddress((void**)&qp, g_q);
    cudaGetSymbolAddress((void**)&kp, g_k);
    cudaGetSymbolAddress((void**)&vp, g_v);
    cudaGetSymbolAddress((void**)&zp, g_z);
    cudaGetSymbolAddress((void**)&wt, g_wt);
    float* wq = wt;
    float* wk = wt + DH * DH;
    float* wv = wt + 2 * DH * DH;
    float* wo = wt + 3 * DH * DH;

    cudaFuncSetAttribute(gemm_cp_kernel<true>,
                         cudaFuncAttributeMaxDynamicSharedMemorySize, GEMM_SMEM);
    cudaFuncSetAttribute(gemm_cp_kernel<false>,
                         cudaFuncAttributeMaxDynamicSharedMemorySize, GEMM_SMEM);
    cudaFuncSetAttribute(attn_kernel,
                         cudaFuncAttributeMaxDynamicSharedMemorySize, ATTN_SMEM);

    // 0. pre-round weights to tf32
    int wblocks = DH * DH / 1024;
    wcvt_kernel<<<wblocks, 256>>>(Wq, wq);
    wcvt_kernel<<<wblocks, 256>>>(Wk, wk);
    wcvt_kernel<<<wblocks, 256>>>(Wv, wv);
    wcvt_kernel<<<wblocks, 256>>>(Wo, wo);

    // 1. LayerNorm (tf32-rounded output)
    ln_kernel<<<MROWS, 256>>>(x, gamma, beta, xn);

    // 2. Q/K/V projections (round outputs for attention consumption)
    dim3 ggrid(GN / 128, GM / 128);
    gemm_cp_kernel<true><<<ggrid, 256, GEMM_SMEM>>>(xn, wq, bq, qp);
    gemm_cp_kernel<true><<<ggrid, 256, GEMM_SMEM>>>(xn, wk, bk, kp);
    gemm_cp_kernel<true><<<ggrid, 256, GEMM_SMEM>>>(xn, wv, bv, vp);

    // 3. causal multi-head attention
    dim3 agrid(SEQ / BQ, NH, NB);
    attn_kernel<<<agrid, 256, ATTN_SMEM>>>(qp, kp, vp, zp);

    // 4. output projection (full fp32 output)
    gemm_cp_kernel<false><<<ggrid, 256, GEMM_SMEM>>>(zp, wo, bo, out);
}

// round 8
// speedup vs baseline: 1.7255x; 1.0471x over previous
#include <cuda_runtime.h>
#include <cuda_bf16.h>
#include <math.h>
#include <stdint.h>

// Problem constants
#define NB   4
#define SEQ  2048
#define DH   1024
#define NH   16
#define HD   64
#define MROWS (NB*SEQ)          // 8192

#define GM MROWS
#define GN DH
#define GK DH

// ---------------- scratch (static device globals; no allocation) -------------
__device__ float g_xn[MROWS * DH];
__device__ float g_q [MROWS * DH];
__device__ float g_k [MROWS * DH];
__device__ float g_v [MROWS * DH];
__device__ float g_z [MROWS * DH];
__device__ float g_wt[4][DH * DH];     // tf32-rounded weights (q,k,v,o packed)
__device__ float g_bqkv[3 * DH];       // packed q,k,v biases

// ---------------------------- helpers -----------------------------------------
__device__ __forceinline__ float f_tf32(float x) {
    uint32_t r;
    asm("cvt.rna.tf32.f32 %0, %1;" : "=r"(r) : "f"(x));
    return __uint_as_float(r);
}

__device__ __forceinline__ void mma_tf32(float* c, const float* a, const float* b) {
    asm volatile(
        "mma.sync.aligned.m16n8k8.row.col.f32.tf32.tf32.f32 "
        "{%0,%1,%2,%3}, {%4,%5,%6,%7}, {%8,%9}, {%0,%1,%2,%3};\n"
        : "+f"(c[0]), "+f"(c[1]), "+f"(c[2]), "+f"(c[3])
        : "r"(__float_as_uint(a[0])), "r"(__float_as_uint(a[1])),
          "r"(__float_as_uint(a[2])), "r"(__float_as_uint(a[3])),
          "r"(__float_as_uint(b[0])), "r"(__float_as_uint(b[1])));
}

__device__ __forceinline__ void cp_async16(void* smem, const void* gmem) {
    uint32_t s = (uint32_t)__cvta_generic_to_shared(smem);
    asm volatile("cp.async.cg.shared.global [%0], [%1], 16;" :: "r"(s), "l"(gmem));
}
__device__ __forceinline__ void cp_commit() {
    asm volatile("cp.async.commit_group;");
}
template<int N>
__device__ __forceinline__ void cp_wait() {
    asm volatile("cp.async.wait_group %0;" :: "n"(N));
}

// ----------------- weight pre-round (tf32) + bias pack -------------------------
__global__ __launch_bounds__(256) void wcvt_kernel(
    const float* __restrict__ w0, const float* __restrict__ w1,
    const float* __restrict__ w2, const float* __restrict__ w3,
    float* __restrict__ dst)
{
    const float* srcs[4] = {w0, w1, w2, w3};
    const float* src = srcs[blockIdx.y];
    float* d = dst + (size_t)blockIdx.y * DH * DH;
    int i = (blockIdx.x * 256 + threadIdx.x) * 4;
    float4 v = *(const float4*)&src[i];
    *(float4*)&d[i] = make_float4(f_tf32(v.x), f_tf32(v.y),
                                  f_tf32(v.z), f_tf32(v.w));
}

__global__ __launch_bounds__(256) void bpack_kernel(
    const float* __restrict__ b0, const float* __restrict__ b1,
    const float* __restrict__ b2, float* __restrict__ dst)
{
    int i = blockIdx.x * 256 + threadIdx.x;
    dst[i]            = b0[i];
    dst[i + DH]       = b1[i];
    dst[i + 2 * DH]   = b2[i];
}

// ---------------------- LayerNorm (warp per row, tf32 out) ---------------------
__global__ __launch_bounds__(256) void ln_kernel(
    const float* __restrict__ x, const float* __restrict__ gamma,
    const float* __restrict__ beta, float* __restrict__ xn)
{
    int warp = threadIdx.x >> 5, lane = threadIdx.x & 31;
    int row = blockIdx.x * 8 + warp;
    const float* xr = x + (size_t)row * DH;
    float* outr = xn + (size_t)row * DH;

    float4 v[8];
    float s = 0.f, sq = 0.f;
    #pragma unroll
    for (int j = 0; j < 8; j++) {
        v[j] = *(const float4*)&xr[(j * 32 + lane) * 4];
        s  += v[j].x + v[j].y + v[j].z + v[j].w;
        sq += v[j].x * v[j].x + v[j].y * v[j].y
            + v[j].z * v[j].z + v[j].w * v[j].w;
    }
    #pragma unroll
    for (int off = 16; off > 0; off >>= 1) {
        s  += __shfl_xor_sync(0xffffffffu, s,  off);
        sq += __shfl_xor_sync(0xffffffffu, sq, off);
    }
    float mu  = s * (1.0f / DH);
    float var = sq * (1.0f / DH) - mu * mu;
    float inv = rsqrtf(var + 1e-5f);

    #pragma unroll
    for (int j = 0; j < 8; j++) {
        int c = (j * 32 + lane) * 4;
        float4 g = *(const float4*)&gamma[c];
        float4 b = *(const float4*)&beta[c];
        float4 o;
        o.x = f_tf32((v[j].x - mu) * inv * g.x + b.x);
        o.y = f_tf32((v[j].y - mu) * inv * g.y + b.y);
        o.z = f_tf32((v[j].z - mu) * inv * g.z + b.z);
        o.w = f_tf32((v[j].w - mu) * inv * g.w + b.w);
        *(float4*)&outr[c] = o;
    }
}

// ----------- GEMM core (tf32, cp.async 2-stage): acc = A @ W^T ----------------
#define SA 36
#define GTILE (128 * SA)
#define GEMM_SMEM (4 * GTILE * (int)sizeof(float))

struct GemmCore {
    float acc[4][4][4];
    int t, lane, wid, lr, lc, m_base, n_base;

    __device__ __forceinline__ void init(int tid) {
        t = tid; lane = t & 31; wid = t >> 5;
        lr = lane >> 2; lc = lane & 3;
        m_base = (wid & 1) * 64;
        n_base = (wid >> 1) * 32;
        #pragma unroll
        for (int i = 0; i < 4; i++)
            #pragma unroll
            for (int j = 0; j < 4; j++)
                #pragma unroll
                for (int e = 0; e < 4; e++) acc[i][j][e] = 0.f;
    }

    __device__ __forceinline__ void run(
        float* As, float* Bs,
        const float* __restrict__ A, const float* __restrict__ W,
        int m0, int n0)
    {
        #pragma unroll
        for (int i = 0; i < 4; i++) {
            int e = t + i * 256;
            int row = e >> 3, c4 = (e & 7) * 4;
            cp_async16(&As[row * SA + c4], &A[(size_t)(m0 + row) * GK + c4]);
            cp_async16(&Bs[row * SA + c4], &W[(size_t)(n0 + row) * GK + c4]);
        }
        cp_commit();

        int buf = 0;
        for (int k0 = 0; k0 < GK; k0 += 32) {
            bool more = (k0 + 32 < GK);
            if (more) {
                float* Aw = &As[(buf ^ 1) * GTILE];
                float* Bw = &Bs[(buf ^ 1) * GTILE];
                #pragma unroll
                for (int i = 0; i < 4; i++) {
                    int e = t + i * 256;
                    int row = e >> 3, c4 = (e & 7) * 4;
                    cp_async16(&Aw[row * SA + c4],
                               &A[(size_t)(m0 + row) * GK + k0 + 32 + c4]);
                    cp_async16(&Bw[row * SA + c4],
                               &W[(size_t)(n0 + row) * GK + k0 + 32 + c4]);
                }
                cp_commit();
                cp_wait<1>();
            } else {
                cp_wait<0>();
            }
            __syncthreads();

            const float* Ab = &As[buf * GTILE];
            const float* Bb = &Bs[buf * GTILE];
            #pragma unroll
            for (int kk = 0; kk < 4; kk++) {
                int kb = kk * 8;
                float a[4][4], b[4][2];
                #pragma unroll
                for (int mf = 0; mf < 4; mf++) {
                    int row = m_base + mf * 16 + lr;
                    a[mf][0] = Ab[row * SA + kb + lc];
                    a[mf][1] = Ab[(row + 8) * SA + kb + lc];
                    a[mf][2] = Ab[row * SA + kb + 4 + lc];
                    a[mf][3] = Ab[(row + 8) * SA + kb + 4 + lc];
                }
                #pragma unroll
                for (int nf = 0; nf < 4; nf++) {
                    int col = n_base + nf * 8 + lr;
                    b[nf][0] = Bb[col * SA + kb + lc];
                    b[nf][1] = Bb[col * SA + kb + 4 + lc];
                }
                #pragma unroll
                for (int mf = 0; mf < 4; mf++)
                    #pragma unroll
                    for (int nf = 0; nf < 4; nf++)
                        mma_tf32(acc[mf][nf], a[mf], b[nf]);
            }
            __syncthreads();
            buf ^= 1;
        }
    }

    template<bool ROUND_OUT>
    __device__ __forceinline__ void store(
        const float* __restrict__ bias, float* __restrict__ C,
        int m0, int ncol0)
    {
        #pragma unroll
        for (int nf = 0; nf < 4; nf++) {
            int col = ncol0 + n_base + nf * 8 + 2 * lc;
            float b0 = bias[col - ncol0 + (ncol0 & 0)] , b1;
            // bias indexed by packed col; caller passes bias already offset
            b0 = bias[n_base + nf * 8 + 2 * lc];
            b1 = bias[n_base + nf * 8 + 2 * lc + 1];
            #pragma unroll
            for (int mf = 0; mf < 4; mf++) {
                int row = m0 + m_base + mf * 16 + lr;
                float v0 = acc[mf][nf][0] + b0, v1 = acc[mf][nf][1] + b1;
                float v2 = acc[mf][nf][2] + b0, v3 = acc[mf][nf][3] + b1;
                if (ROUND_OUT) {
                    v0 = f_tf32(v0); v1 = f_tf32(v1);
                    v2 = f_tf32(v2); v3 = f_tf32(v3);
                }
                *(float2*)&C[(size_t)row * GN + col]       = make_float2(v0, v1);
                *(float2*)&C[(size_t)(row + 8) * GN + col] = make_float2(v2, v3);
            }
        }
    }
};

// Fused QKV: Wpacked [3072 x 1024], biasPacked [3072]; routes output by n-block.
__global__ __launch_bounds__(256, 2) void gemm_qkv_kernel(
    const float* __restrict__ A, const float* __restrict__ Wp,
    const float* __restrict__ bp,
    float* __restrict__ q, float* __restrict__ k, float* __restrict__ v)
{
    extern __shared__ float gsm[];
    GemmCore core;
    core.init(threadIdx.x);

    int npack0 = blockIdx.x * 128;        // 0..2944
    int m0 = blockIdx.y * 128;
    int mat = npack0 >> 10;               // 0=q 1=k 2=v (128-aligned blocks)
    int ncol0 = npack0 & 1023;

    core.run(gsm, gsm + 2 * GTILE, A, Wp + (size_t)npack0 * GK, m0, 0);

    float* C = (mat == 0) ? q : (mat == 1) ? k : v;
    core.store<true>(bp + npack0, C, m0, ncol0);
}

// Plain GEMM (output projection)
__global__ __launch_bounds__(256, 2) void gemm_o_kernel(
    const float* __restrict__ A, const float* __restrict__ W,
    const float* __restrict__ bias, float* __restrict__ C)
{
    extern __shared__ float gsm[];
    GemmCore core;
    core.init(threadIdx.x);
    int n0 = blockIdx.x * 128;
    int m0 = blockIdx.y * 128;
    core.run(gsm, gsm + 2 * GTILE, A, W + (size_t)n0 * GK, m0, 0);
    core.store<false>(bias + n0, C, m0, n0);
}

// ------------------- Flash Attention (tf32, split K/V wait) --------------------
#define BQ  128
#define BKT 64
#define AST 68
#define ATTN_SMEM ((BQ*AST + BKT*AST + BKT*AST + BQ*AST) * (int)sizeof(float))

__global__ __launch_bounds__(256, 2) void attn_kernel(
    const float* __restrict__ q, const float* __restrict__ k,
    const float* __restrict__ v, float* __restrict__ z)
{
    extern __shared__ float sm[];
    float* Qs = sm;                    // [128 r][AST]
    float* Ks = Qs + BQ * AST;         // [64 y][AST]
    float* Vs = Ks + BKT * AST;        // [64 y][AST]
    float* Ps = Vs + BKT * AST;        // [128 r][AST] per-warp stripes

    int xc = (gridDim.x - 1) - blockIdx.x;   // heavy tiles first
    int h  = blockIdx.y;
    int n  = blockIdx.z;
    int x0 = xc * BQ;
    int t    = threadIdx.x;
    int lane = t & 31;
    int wid  = t >> 5;
    int lr = lane >> 2;
    int lc = lane & 3;
    int m_base = wid * 16;
    float* Pw = Ps + m_base * AST;

    const float* qb = q + ((size_t)n * SEQ) * DH + h * HD;
    const float* kb = k + ((size_t)n * SEQ) * DH + h * HD;
    const float* vb = v + ((size_t)n * SEQ) * DH + h * HD;

    // stage Q via cp.async (own group; completes before first wait<1> passes K)
    #pragma unroll
    for (int i = 0; i < 8; i++) {
        int f = t + i * 256;
        int r = f >> 4, c4 = (f & 15) * 4;
        cp_async16(&Qs[r * AST + c4], &qb[(size_t)(x0 + r) * DH + c4]);
    }
    cp_commit();

    float m_lo = -INFINITY, m_hi = -INFINITY, l_lo = 0.f, l_hi = 0.f;
    float o[8][4];
    #pragma unroll
    for (int nf = 0; nf < 8; nf++)
        #pragma unroll
        for (int e = 0; e < 4; e++) o[nf][e] = 0.f;

    int yend = x0 + BQ;
    for (int y0 = 0; y0 < yend; y0 += BKT) {
        __syncthreads();   // prior iter reads of Ks/Vs done
        // K group
        #pragma unroll
        for (int i = 0; i < 4; i++) {
            int f = t + i * 256;
            int y = f >> 4, c4 = (f & 15) * 4;
            cp_async16(&Ks[y * AST + c4], &kb[(size_t)(y0 + y) * DH + c4]);
        }
        cp_commit();
        // V group (waited only after softmax)
        #pragma unroll
        for (int i = 0; i < 4; i++) {
            int f = t + i * 256;
            int y = f >> 4, c4 = (f & 15) * 4;
            cp_async16(&Vs[y * AST + c4], &vb[(size_t)(y0 + y) * DH + c4]);
        }
        cp_commit();

        cp_wait<1>();      // K (and Q on iter 0) complete; V may be in flight
        __syncthreads();

        // ---- S = Q K^T : warp computes 16 x 64 ----
        float s[8][4];
        #pragma unroll
        for (int nf = 0; nf < 8; nf++)
            #pragma unroll
            for (int e = 0; e < 4; e++) s[nf][e] = 0.f;

        #pragma unroll
        for (int kk = 0; kk < 8; kk++) {
            int kb8 = kk * 8;
            float a[4];
            int row = m_base + lr;
            a[0] = Qs[row * AST + kb8 + lc];
            a[1] = Qs[(row + 8) * AST + kb8 + lc];
            a[2] = Qs[row * AST + kb8 + 4 + lc];
            a[3] = Qs[(row + 8) * AST + kb8 + 4 + lc];
            #pragma unroll
            for (int nf = 0; nf < 8; nf++) {
                float b[2];
                int y = nf * 8 + lr;
                b[0] = Ks[y * AST + kb8 + lc];
                b[1] = Ks[y * AST + kb8 + 4 + lc];
                mma_tf32(s[nf], a, b);
            }
        }

        // scale (exact pow2)
        #pragma unroll
        for (int nf = 0; nf < 8; nf++) {
            s[nf][0] *= 0.125f; s[nf][1] *= 0.125f;
            s[nf][2] *= 0.125f; s[nf][3] *= 0.125f;
        }

        // ---- causal mask (only straddling tiles) ----
        if (y0 + BKT - 1 > x0) {
            int r_lo = x0 + m_base + lr;
            #pragma unroll
            for (int nf = 0; nf < 8; nf++) {
                int c = y0 + nf * 8 + 2 * lc;
                if (c     > r_lo) s[nf][0] = -INFINITY;
                if (c + 1 > r_lo) s[nf][1] = -INFINITY;
                if (c     > r_lo + 8) s[nf][2] = -INFINITY;
                if (c + 1 > r_lo + 8) s[nf][3] = -INFINITY;
            }
        }

        // ---- online softmax (4-lane row groups) ----
        float mt_lo = -INFINITY, mt_hi = -INFINITY;
        #pragma unroll
        for (int nf = 0; nf < 8; nf++) {
            mt_lo = fmaxf(mt_lo, fmaxf(s[nf][0], s[nf][1]));
            mt_hi = fmaxf(mt_hi, fmaxf(s[nf][2], s[nf][3]));
        }
        #pragma unroll
        for (int off = 1; off <= 2; off <<= 1) {
            mt_lo = fmaxf(mt_lo, __shfl_xor_sync(0xffffffffu, mt_lo, off));
            mt_hi = fmaxf(mt_hi, __shfl_xor_sync(0xffffffffu, mt_hi, off));
        }
        float mn_lo = fmaxf(m_lo, mt_lo);
        float mn_hi = fmaxf(m_hi, mt_hi);
        float al_lo = __expf(m_lo - mn_lo);
        float al_hi = __expf(m_hi - mn_hi);
        m_lo = mn_lo; m_hi = mn_hi;

        float rs_lo = 0.f, rs_hi = 0.f;
        #pragma unroll
        for (int nf = 0; nf < 8; nf++) {
            s[nf][0] = __expf(s[nf][0] - mn_lo);
            s[nf][1] = __expf(s[nf][1] - mn_lo);
            s[nf][2] = __expf(s[nf][2] - mn_hi);
            s[nf][3] = __expf(s[nf][3] - mn_hi);
            rs_lo += s[nf][0] + s[nf][1];
            rs_hi += s[nf][2] + s[nf][3];
        }
        #pragma unroll
        for (int off = 1; off <= 2; off <<= 1) {
            rs_lo += __shfl_xor_sync(0xffffffffu, rs_lo, off);
            rs_hi += __shfl_xor_sync(0xffffffffu, rs_hi, off);
        }
        l_lo = l_lo * al_lo + rs_lo;
        l_hi = l_hi * al_hi + rs_hi;
        #pragma unroll
        for (int nf = 0; nf < 8; nf++) {
            o[nf][0] *= al_lo; o[nf][1] *= al_lo;
            o[nf][2] *= al_hi; o[nf][3] *= al_hi;
        }

        // ---- stage P (warp-private stripe; tf32-rounded) ----
        #pragma unroll
        for (int nf = 0; nf < 8; nf++) {
            int c = nf * 8 + 2 * lc;
            *(float2*)&Pw[lr * AST + c]       =
                make_float2(f_tf32(s[nf][0]), f_tf32(s[nf][1]));
            *(float2*)&Pw[(lr + 8) * AST + c] =
                make_float2(f_tf32(s[nf][2]), f_tf32(s[nf][3]));
        }

        cp_wait<0>();      // V complete
        __syncthreads();   // V visible to all; also covers Pw via barrier

        // ---- O += P V : warp computes 16 x 64 ----
        #pragma unroll
        for (int kk = 0; kk < 8; kk++) {
            int kb8 = kk * 8;
            float a[4];
            a[0] = Pw[lr * AST + kb8 + lc];
            a[1] = Pw[(lr + 8) * AST + kb8 + lc];
            a[2] = Pw[lr * AST + kb8 + 4 + lc];
            a[3] = Pw[(lr + 8) * AST + kb8 + 4 + lc];
            #pragma unroll
            for (int nf = 0; nf < 8; nf++) {
                float b[2];
                int d = nf * 8 + lr;
                b[0] = Vs[(kb8 + lc) * AST + d];
                b[1] = Vs[(kb8 + 4 + lc) * AST + d];
                mma_tf32(o[nf], a, b);
            }
        }
        __syncwarp();
    }

    // ---- normalize + store (tf32-rounded: feeds final GEMM) ----
    float inv_lo = 1.0f / l_lo;
    float inv_hi = 1.0f / l_hi;
    int r_lo = x0 + m_base + lr;
    #pragma unroll
    for (int nf = 0; nf < 8; nf++) {
        int d = nf * 8 + 2 * lc;
        float* zlo = &z[((size_t)n * SEQ + r_lo) * DH + h * HD + d];
        float* zhi = &z[((size_t)n * SEQ + r_lo + 8) * DH + h * HD + d];
        *(float2*)zlo = make_float2(f_tf32(o[nf][0] * inv_lo),
                                    f_tf32(o[nf][1] * inv_lo));
        *(float2*)zhi = make_float2(f_tf32(o[nf][2] * inv_hi),
                                    f_tf32(o[nf][3] * inv_hi));
    }
}

// ------------------------------ launcher --------------------------------------
extern "C" void kernel_launch(void* const* d_in, const int* in_sizes, int n_in,
                              void* d_out, int out_size)
{
    const float* x     = (const float*)d_in[0];
    const float* Wq    = (const float*)d_in[1];
    const float* bq    = (const float*)d_in[2];
    const float* Wk    = (const float*)d_in[3];
    const float* bk    = (const float*)d_in[4];
    const float* Wv    = (const float*)d_in[5];
    const float* bv    = (const float*)d_in[6];
    const float* Wo    = (const float*)d_in[7];
    const float* bo    = (const float*)d_in[8];
    const float* gamma = (const float*)d_in[9];
    const float* beta  = (const float*)d_in[10];
    float* out = (float*)d_out;

    float *xn, *qp, *kp, *vp, *zp, *wt, *bqkv;
    cudaGetSymbolAddress((void**)&xn, g_xn);
    cudaGetSymbolAddress((void**)&qp, g_q);
    cudaGetSymbolAddress((void**)&kp, g_k);
    cudaGetSymbolAddress((void**)&vp, g_v);
    cudaGetSymbolAddress((void**)&zp, g_z);
    cudaGetSymbolAddress((void**)&wt, g_wt);
    cudaGetSymbolAddress((void**)&bqkv, g_bqkv);
    float* wqkv = wt;                    // [3072 x 1024] packed
    float* wo   = wt + 3 * DH * DH;

    cudaFuncSetAttribute(gemm_qkv_kernel,
                         cudaFuncAttributeMaxDynamicSharedMemorySize, GEMM_SMEM);
    cudaFuncSetAttribute(gemm_o_kernel,
                         cudaFuncAttributeMaxDynamicSharedMemorySize, GEMM_SMEM);
    cudaFuncSetAttribute(attn_kernel,
                         cudaFuncAttributeMaxDynamicSharedMemorySize, ATTN_SMEM);

    // 0. pre-round weights (one launch) + pack biases
    dim3 wgrid(DH * DH / 1024, 4);
    wcvt_kernel<<<wgrid, 256>>>(Wq, Wk, Wv, Wo, wt);
    bpack_kernel<<<DH / 256, 256>>>(bq, bk, bv, bqkv);

    // 1. LayerNorm (warp per row, tf32-rounded output)
    ln_kernel<<<MROWS / 8, 256>>>(x, gamma, beta, xn);

    // 2. fused Q/K/V projection (one GEMM over packed weights)
    dim3 qkvgrid(3 * GN / 128, GM / 128);
    gemm_qkv_kernel<<<qkvgrid, 256, GEMM_SMEM>>>(xn, wqkv, bqkv, qp, kp, vp);

    // 3. causal multi-head attention
    dim3 agrid(SEQ / BQ, NH, NB);
    attn_kernel<<<agrid, 256, ATTN_SMEM>>>(qp, kp, vp, zp);

    // 4. output projection (full fp32 output)
    dim3 ogrid(GN / 128, GM / 128);
    gemm_o_kernel<<<ogrid, 256, GEMM_SMEM>>>(zp, wo, bo, out);
}

// round 9
// speedup vs baseline: 2.0416x; 1.1832x over previous
#include <cuda_runtime.h>
#include <cuda_bf16.h>
#include <math.h>
#include <stdint.h>

// Problem constants
#define NB   4
#define SEQ  2048
#define DH   1024
#define NH   16
#define HD   64
#define MROWS (NB*SEQ)          // 8192

#define GM MROWS
#define GN DH
#define GK DH

// ---------------- scratch (static device globals; no allocation) -------------
__device__ float g_xn[MROWS * DH];      // permuted cols
__device__ float g_q [MROWS * DH];      // permuted cols
__device__ float g_k [MROWS * DH];      // permuted cols
__device__ float g_v [MROWS * DH];      // TRANSPOSED: [NB][NH][HD][SEQ], y permuted
__device__ float g_z [MROWS * DH];      // permuted cols
__device__ float g_wt[4][DH * DH];      // tf32, permuted cols (q,k,v,o)
__device__ float g_bqkv[3 * DH];        // packed biases (logical order)

// ---------------------------- helpers -----------------------------------------
// per-8 column permutation: logical j -> position 2*(j&3) + (j>>2)
// => mma k-pair (lc, lc+4) lands at adjacent positions (2lc, 2lc+1)
__device__ __forceinline__ int pi8(int j) { return ((j & 3) << 1) | (j >> 2); }

__device__ __forceinline__ float f_tf32(float x) {
    uint32_t r;
    asm("cvt.rna.tf32.f32 %0, %1;" : "=r"(r) : "f"(x));
    return __uint_as_float(r);
}

__device__ __forceinline__ void mma_tf32(float* c, const float* a, const float* b) {
    asm volatile(
        "mma.sync.aligned.m16n8k8.row.col.f32.tf32.tf32.f32 "
        "{%0,%1,%2,%3}, {%4,%5,%6,%7}, {%8,%9}, {%0,%1,%2,%3};\n"
        : "+f"(c[0]), "+f"(c[1]), "+f"(c[2]), "+f"(c[3])
        : "r"(__float_as_uint(a[0])), "r"(__float_as_uint(a[1])),
          "r"(__float_as_uint(a[2])), "r"(__float_as_uint(a[3])),
          "r"(__float_as_uint(b[0])), "r"(__float_as_uint(b[1])));
}

__device__ __forceinline__ void cp_async16(void* smem, const void* gmem) {
    uint32_t s = (uint32_t)__cvta_generic_to_shared(smem);
    asm volatile("cp.async.cg.shared.global [%0], [%1], 16;" :: "r"(s), "l"(gmem));
}
__device__ __forceinline__ void cp_commit() {
    asm volatile("cp.async.commit_group;");
}
template<int N>
__device__ __forceinline__ void cp_wait() {
    asm volatile("cp.async.wait_group %0;" :: "n"(N));
}

// ----------------- weight pre-round (tf32) + permute + bias pack ---------------
__global__ __launch_bounds__(256) void wcvt_kernel(
    const float* __restrict__ w0, const float* __restrict__ w1,
    const float* __restrict__ w2, const float* __restrict__ w3,
    float* __restrict__ dst)
{
    const float* srcs[4] = {w0, w1, w2, w3};
    const float* src = srcs[blockIdx.y];
    float* d = dst + (size_t)blockIdx.y * DH * DH;
    int i = (blockIdx.x * 256 + threadIdx.x) * 4;
    float4 v = *(const float4*)&src[i];
    int base = i & ~7;
    int j0 = i & 7;          // 0 or 4
    d[base + pi8(j0 + 0)] = f_tf32(v.x);
    d[base + pi8(j0 + 1)] = f_tf32(v.y);
    d[base + pi8(j0 + 2)] = f_tf32(v.z);
    d[base + pi8(j0 + 3)] = f_tf32(v.w);
}

__global__ __launch_bounds__(256) void bpack_kernel(
    const float* __restrict__ b0, const float* __restrict__ b1,
    const float* __restrict__ b2, float* __restrict__ dst)
{
    int i = blockIdx.x * 256 + threadIdx.x;
    dst[i]          = b0[i];
    dst[i + DH]     = b1[i];
    dst[i + 2 * DH] = b2[i];
}

// ---------------- LayerNorm (warp per row, tf32 + permuted out) ----------------
__global__ __launch_bounds__(256) void ln_kernel(
    const float* __restrict__ x, const float* __restrict__ gamma,
    const float* __restrict__ beta, float* __restrict__ xn)
{
    int warp = threadIdx.x >> 5, lane = threadIdx.x & 31;
    int row = blockIdx.x * 8 + warp;
    const float* xr = x + (size_t)row * DH;
    float* outr = xn + (size_t)row * DH;

    float4 v[8];
    float s = 0.f, sq = 0.f;
    #pragma unroll
    for (int j = 0; j < 8; j++) {
        v[j] = *(const float4*)&xr[(j * 32 + lane) * 4];
        s  += v[j].x + v[j].y + v[j].z + v[j].w;
        sq += v[j].x * v[j].x + v[j].y * v[j].y
            + v[j].z * v[j].z + v[j].w * v[j].w;
    }
    #pragma unroll
    for (int off = 16; off > 0; off >>= 1) {
        s  += __shfl_xor_sync(0xffffffffu, s,  off);
        sq += __shfl_xor_sync(0xffffffffu, sq, off);
    }
    float mu  = s * (1.0f / DH);
    float var = sq * (1.0f / DH) - mu * mu;
    float inv = rsqrtf(var + 1e-5f);

    #pragma unroll
    for (int j = 0; j < 8; j++) {
        int c = (j * 32 + lane) * 4;
        float4 g = *(const float4*)&gamma[c];
        float4 b = *(const float4*)&beta[c];
        int base = c & ~7;
        int j0 = c & 7;
        outr[base + pi8(j0 + 0)] = f_tf32((v[j].x - mu) * inv * g.x + b.x);
        outr[base + pi8(j0 + 1)] = f_tf32((v[j].y - mu) * inv * g.y + b.y);
        outr[base + pi8(j0 + 2)] = f_tf32((v[j].z - mu) * inv * g.z + b.z);
        outr[base + pi8(j0 + 3)] = f_tf32((v[j].w - mu) * inv * g.w + b.w);
    }
}

// ----------- GEMM core (tf32, cp.async 2-stage, pair-layout LDS.64) -----------
// Smem row stride SA=40 (≡8 mod 32 -> conflict-free LDS.64 fragments).
#define SA 40
#define GTILE (128 * SA)
#define GEMM_SMEM (4 * GTILE * (int)sizeof(float))

struct GemmCore {
    float acc[4][4][4];
    int t, lane, wid, lr, lc, m_base, n_base;

    __device__ __forceinline__ void init(int tid) {
        t = tid; lane = t & 31; wid = t >> 5;
        lr = lane >> 2; lc = lane & 3;
        m_base = (wid & 1) * 64;
        n_base = (wid >> 1) * 32;
        #pragma unroll
        for (int i = 0; i < 4; i++)
            #pragma unroll
            for (int j = 0; j < 4; j++)
                #pragma unroll
                for (int e = 0; e < 4; e++) acc[i][j][e] = 0.f;
    }

    __device__ __forceinline__ void run(
        float* As, float* Bs,
        const float* __restrict__ A, const float* __restrict__ W, int m0)
    {
        #pragma unroll
        for (int i = 0; i < 4; i++) {
            int e = t + i * 256;
            int row = e >> 3, c4 = (e & 7) * 4;
            cp_async16(&As[row * SA + c4], &A[(size_t)(m0 + row) * GK + c4]);
            cp_async16(&Bs[row * SA + c4], &W[(size_t)row * GK + c4]);
        }
        cp_commit();

        int buf = 0;
        for (int k0 = 0; k0 < GK; k0 += 32) {
            bool more = (k0 + 32 < GK);
            if (more) {
                float* Aw = &As[(buf ^ 1) * GTILE];
                float* Bw = &Bs[(buf ^ 1) * GTILE];
                #pragma unroll
                for (int i = 0; i < 4; i++) {
                    int e = t + i * 256;
                    int row = e >> 3, c4 = (e & 7) * 4;
                    cp_async16(&Aw[row * SA + c4],
                               &A[(size_t)(m0 + row) * GK + k0 + 32 + c4]);
                    cp_async16(&Bw[row * SA + c4],
                               &W[(size_t)row * GK + k0 + 32 + c4]);
                }
                cp_commit();
                cp_wait<1>();
            } else {
                cp_wait<0>();
            }
            __syncthreads();

            const float* Ab = &As[buf * GTILE];
            const float* Bb = &Bs[buf * GTILE];
            #pragma unroll
            for (int kk = 0; kk < 4; kk++) {
                int kb = kk * 8 + 2 * lc;
                float a[4][4], b[4][2];
                #pragma unroll
                for (int mf = 0; mf < 4; mf++) {
                    int row = m_base + mf * 16 + lr;
                    float2 lo = *(const float2*)&Ab[row * SA + kb];
                    float2 hi = *(const float2*)&Ab[(row + 8) * SA + kb];
                    a[mf][0] = lo.x; a[mf][1] = hi.x;
                    a[mf][2] = lo.y; a[mf][3] = hi.y;
                }
                #pragma unroll
                for (int nf = 0; nf < 4; nf++) {
                    int col = n_base + nf * 8 + lr;
                    float2 bb = *(const float2*)&Bb[col * SA + kb];
                    b[nf][0] = bb.x; b[nf][1] = bb.y;
                }
                #pragma unroll
                for (int mf = 0; mf < 4; mf++)
                    #pragma unroll
                    for (int nf = 0; nf < 4; nf++)
                        mma_tf32(acc[mf][nf], a[mf], b[nf]);
            }
            __syncthreads();
            buf ^= 1;
        }
    }
};

// Fused QKV GEMM. Wp: [3072 x 1024] permuted-col. Writes q,k permuted-col;
// v transposed [NB][NH][HD][SEQ] with y permuted (for attention PV).
__global__ __launch_bounds__(256, 2) void gemm_qkv_kernel(
    const float* __restrict__ A, const float* __restrict__ Wp,
    const float* __restrict__ bp,
    float* __restrict__ q, float* __restrict__ k, float* __restrict__ v)
{
    extern __shared__ float gsm[];
    GemmCore core;
    core.init(threadIdx.x);

    int npack0 = blockIdx.x * 128;
    int m0 = blockIdx.y * 128;
    int mat = npack0 >> 10;               // 0=q 1=k 2=v
    int ncol0 = npack0 & 1023;

    core.run(gsm, gsm + 2 * GTILE, A, Wp + (size_t)npack0 * GK, m0);

    const float* bias = bp + npack0;
    int lr = core.lr, lc = core.lc;
    int p0 = pi8(2 * lc), p1 = pi8(2 * lc + 1);

    #pragma unroll
    for (int nf = 0; nf < 4; nf++) {
        int cb = core.n_base + nf * 8;          // col block base (logical, %8==0)
        float b0 = bias[cb + 2 * lc];
        float b1 = bias[cb + 2 * lc + 1];
        #pragma unroll
        for (int mf = 0; mf < 4; mf++) {
            int row = m0 + core.m_base + mf * 16 + lr;
            float v0 = f_tf32(core.acc[mf][nf][0] + b0);
            float v1 = f_tf32(core.acc[mf][nf][1] + b1);
            float v2 = f_tf32(core.acc[mf][nf][2] + b0);
            float v3 = f_tf32(core.acc[mf][nf][3] + b1);
            if (mat == 2) {
                // transposed: v[(nb*DH + c)*SEQ + perm_y]
                int c0 = ncol0 + cb + 2 * lc;
                int yl = row & (SEQ - 1);
                int py = (yl & ~7) | pi8(yl & 7);
                size_t b_ = (size_t)(row >> 11) * DH;
                v[(b_ + c0)     * SEQ + py]     = v0;
                v[(b_ + c0 + 1) * SEQ + py]     = v1;
                v[(b_ + c0)     * SEQ + py + 8] = v2;
                v[(b_ + c0 + 1) * SEQ + py + 8] = v3;
            } else {
                float* C = (mat == 0) ? q : k;
                int colb = ncol0 + cb;
                C[(size_t)row * GN + colb + p0]       = v0;
                C[(size_t)row * GN + colb + p1]       = v1;
                C[(size_t)(row + 8) * GN + colb + p0] = v2;
                C[(size_t)(row + 8) * GN + colb + p1] = v3;
            }
        }
    }
}

// Output projection: A (z) permuted-col, W permuted-col, OUTPUT standard layout.
__global__ __launch_bounds__(256, 2) void gemm_o_kernel(
    const float* __restrict__ A, const float* __restrict__ W,
    const float* __restrict__ bias, float* __restrict__ C)
{
    extern __shared__ float gsm[];
    GemmCore core;
    core.init(threadIdx.x);
    int n0 = blockIdx.x * 128;
    int m0 = blockIdx.y * 128;
    core.run(gsm, gsm + 2 * GTILE, A, W + (size_t)n0 * GK, m0);

    int lr = core.lr, lc = core.lc;
    #pragma unroll
    for (int nf = 0; nf < 4; nf++) {
        int col = n0 + core.n_base + nf * 8 + 2 * lc;
        float b0 = bias[col], b1 = bias[col + 1];
        #pragma unroll
        for (int mf = 0; mf < 4; mf++) {
            int row = m0 + core.m_base + mf * 16 + lr;
            *(float2*)&C[(size_t)row * GN + col] =
                make_float2(core.acc[mf][nf][0] + b0, core.acc[mf][nf][1] + b1);
            *(float2*)&C[(size_t)(row + 8) * GN + col] =
                make_float2(core.acc[mf][nf][2] + b0, core.acc[mf][nf][3] + b1);
        }
    }
}

// ------------- Flash Attention (tf32, pair-layout LDS.64, split K/V wait) ------
#define BQ  128
#define BKT 64
#define AST 72      // ≡8 mod 32 -> conflict-free LDS.64
#define ATTN_SMEM ((BQ*AST + BKT*AST + BKT*AST + BQ*AST) * (int)sizeof(float))

__global__ __launch_bounds__(256, 2) void attn_kernel(
    const float* __restrict__ q, const float* __restrict__ k,
    const float* __restrict__ v, float* __restrict__ z)
{
    extern __shared__ float sm[];
    float* Qs = sm;                    // [128 r][AST] permuted d
    float* Ks = Qs + BQ * AST;         // [64 y][AST]  permuted d
    float* Vt = Ks + BKT * AST;        // [64 d][AST]  permuted y (transposed)
    float* Ps = Vt + BKT * AST;        // [128 r][AST] permuted y (per-warp)

    int xc = (gridDim.x - 1) - blockIdx.x;   // heavy tiles first
    int h  = blockIdx.y;
    int n  = blockIdx.z;
    int x0 = xc * BQ;
    int t    = threadIdx.x;
    int lane = t & 31;
    int wid  = t >> 5;
    int lr = lane >> 2;
    int lc = lane & 3;
    int m_base = wid * 16;
    float* Pw = Ps + m_base * AST;
    int pp0 = pi8(2 * lc), pp1 = pi8(2 * lc + 1);

    const float* qb = q + ((size_t)n * SEQ) * DH + h * HD;
    const float* kb = k + ((size_t)n * SEQ) * DH + h * HD;
    const float* vtb = v + ((size_t)(n * NH + h) * HD) * SEQ;  // [64 d][2048 y]

    // stage Q (own cp group)
    #pragma unroll
    for (int i = 0; i < 8; i++) {
        int f = t + i * 256;
        int r = f >> 4, c4 = (f & 15) * 4;
        cp_async16(&Qs[r * AST + c4], &qb[(size_t)(x0 + r) * DH + c4]);
    }
    cp_commit();

    float m_lo = -INFINITY, m_hi = -INFINITY, l_lo = 0.f, l_hi = 0.f;
    float o[8][4];
    #pragma unroll
    for (int nf = 0; nf < 8; nf++)
        #pragma unroll
        for (int e = 0; e < 4; e++) o[nf][e] = 0.f;

    int yend = x0 + BQ;
    for (int y0 = 0; y0 < yend; y0 += BKT) {
        __syncthreads();   // prior iter reads done
        // K group
        #pragma unroll
        for (int i = 0; i < 4; i++) {
            int f = t + i * 256;
            int y = f >> 4, c4 = (f & 15) * 4;
            cp_async16(&Ks[y * AST + c4], &kb[(size_t)(y0 + y) * DH + c4]);
        }
        cp_commit();
        // V group (transposed rows d; y-slice contiguous since permutation is per-8)
        #pragma unroll
        for (int i = 0; i < 4; i++) {
            int f = t + i * 256;
            int d = f >> 4, y4 = (f & 15) * 4;
            cp_async16(&Vt[d * AST + y4], &vtb[(size_t)d * SEQ + y0 + y4]);
        }
        cp_commit();

        cp_wait<1>();      // K (and Q on iter 0) complete; V in flight
        __syncthreads();

        // ---- S = Q K^T ----
        float s[8][4];
        #pragma unroll
        for (int nf = 0; nf < 8; nf++)
            #pragma unroll
            for (int e = 0; e < 4; e++) s[nf][e] = 0.f;

        #pragma unroll
        for (int kk = 0; kk < 8; kk++) {
            int kb8 = kk * 8 + 2 * lc;
            int row = m_base + lr;
            float2 qlo = *(const float2*)&Qs[row * AST + kb8];
            float2 qhi = *(const float2*)&Qs[(row + 8) * AST + kb8];
            float a[4] = {qlo.x, qhi.x, qlo.y, qhi.y};
            #pragma unroll
            for (int nf = 0; nf < 8; nf++) {
                float2 kk2 = *(const float2*)&Ks[(nf * 8 + lr) * AST + kb8];
                float b[2] = {kk2.x, kk2.y};
                mma_tf32(s[nf], a, b);
            }
        }

        // scale (exact pow2)
        #pragma unroll
        for (int nf = 0; nf < 8; nf++) {
            s[nf][0] *= 0.125f; s[nf][1] *= 0.125f;
            s[nf][2] *= 0.125f; s[nf][3] *= 0.125f;
        }

        // ---- causal mask (logical y cols; straddling tiles only) ----
        if (y0 + BKT - 1 > x0) {
            int r_lo = x0 + m_base + lr;
            #pragma unroll
            for (int nf = 0; nf < 8; nf++) {
                int c = y0 + nf * 8 + 2 * lc;
                if (c     > r_lo) s[nf][0] = -INFINITY;
                if (c + 1 > r_lo) s[nf][1] = -INFINITY;
                if (c     > r_lo + 8) s[nf][2] = -INFINITY;
                if (c + 1 > r_lo + 8) s[nf][3] = -INFINITY;
            }
        }

        // ---- online softmax (4-lane row groups) ----
        float mt_lo = -INFINITY, mt_hi = -INFINITY;
        #pragma unroll
        for (int nf = 0; nf < 8; nf++) {
            mt_lo = fmaxf(mt_lo, fmaxf(s[nf][0], s[nf][1]));
            mt_hi = fmaxf(mt_hi, fmaxf(s[nf][2], s[nf][3]));
        }
        #pragma unroll
        for (int off = 1; off <= 2; off <<= 1) {
            mt_lo = fmaxf(mt_lo, __shfl_xor_sync(0xffffffffu, mt_lo, off));
            mt_hi = fmaxf(mt_hi, __shfl_xor_sync(0xffffffffu, mt_hi, off));
        }
        float mn_lo = fmaxf(m_lo, mt_lo);
        float mn_hi = fmaxf(m_hi, mt_hi);
        float al_lo = __expf(m_lo - mn_lo);
        float al_hi = __expf(m_hi - mn_hi);
        m_lo = mn_lo; m_hi = mn_hi;

        float rs_lo = 0.f, rs_hi = 0.f;
        #pragma unroll
        for (int nf = 0; nf < 8; nf++) {
            s[nf][0] = __expf(s[nf][0] - mn_lo);
            s[nf][1] = __expf(s[nf][1] - mn_lo);
            s[nf][2] = __expf(s[nf][2] - mn_hi);
            s[nf][3] = __expf(s[nf][3] - mn_hi);
            rs_lo += s[nf][0] + s[nf][1];
            rs_hi += s[nf][2] + s[nf][3];
        }
        #pragma unroll
        for (int off = 1; off <= 2; off <<= 1) {
            rs_lo += __shfl_xor_sync(0xffffffffu, rs_lo, off);
            rs_hi += __shfl_xor_sync(0xffffffffu, rs_hi, off);
        }
        l_lo = l_lo * al_lo + rs_lo;
        l_hi = l_hi * al_hi + rs_hi;
        #pragma unroll
        for (int nf = 0; nf < 8; nf++) {
            o[nf][0] *= al_lo; o[nf][1] *= al_lo;
            o[nf][2] *= al_hi; o[nf][3] *= al_hi;
        }

        // ---- stage P (warp-private; y permuted per-8, tf32) ----
        #pragma unroll
        for (int nf = 0; nf < 8; nf++) {
            int q0 = nf * 8 + pp0;
            int q1 = nf * 8 + pp1;
            Pw[lr * AST + q0]       = f_tf32(s[nf][0]);
            Pw[lr * AST + q1]       = f_tf32(s[nf][1]);
            Pw[(lr + 8) * AST + q0] = f_tf32(s[nf][2]);
            Pw[(lr + 8) * AST + q1] = f_tf32(s[nf][3]);
        }

        cp_wait<0>();      // V complete
        __syncthreads();   // V visible; also orders Pw within warp

        // ---- O += P V ----
        #pragma unroll
        for (int kk = 0; kk < 8; kk++) {
            int kb8 = kk * 8 + 2 * lc;
            float2 plo = *(const float2*)&Pw[lr * AST + kb8];
            float2 phi = *(const float2*)&Pw[(lr + 8) * AST + kb8];
            float a[4] = {plo.x, phi.x, plo.y, phi.y};
            #pragma unroll
            for (int nf = 0; nf < 8; nf++) {
                float2 vv = *(const float2*)&Vt[(nf * 8 + lr) * AST + kb8];
                float b[2] = {vv.x, vv.y};
                mma_tf32(o[nf], a, b);
            }
        }
        __syncwarp();
    }

    // ---- normalize + store (permuted d cols, tf32: feeds o-proj) ----
    float inv_lo = 1.0f / l_lo;
    float inv_hi = 1.0f / l_hi;
    int r_lo = x0 + m_base + lr;
    #pragma unroll
    for (int nf = 0; nf < 8; nf++) {
        int dbase = h * HD + nf * 8;
        float* zlo = &z[((size_t)n * SEQ + r_lo) * DH + dbase];
        float* zhi = &z[((size_t)n * SEQ + r_lo + 8) * DH + dbase];
        zlo[pp0] = f_tf32(o[nf][0] * inv_lo);
        zlo[pp1] = f_tf32(o[nf][1] * inv_lo);
        zhi[pp0] = f_tf32(o[nf][2] * inv_hi);
        zhi[pp1] = f_tf32(o[nf][3] * inv_hi);
    }
}

// ------------------------------ launcher --------------------------------------
extern "C" void kernel_launch(void* const* d_in, const int* in_sizes, int n_in,
                              void* d_out, int out_size)
{
    const float* x     = (const float*)d_in[0];
    const float* Wq    = (const float*)d_in[1];
    const float* bq    = (const float*)d_in[2];
    const float* Wk    = (const float*)d_in[3];
    const float* bk    = (const float*)d_in[4];
    const float* Wv    = (const float*)d_in[5];
    const float* bv    = (const float*)d_in[6];
    const float* Wo    = (const float*)d_in[7];
    const float* bo    = (const float*)d_in[8];
    const float* gamma = (const float*)d_in[9];
    const float* beta  = (const float*)d_in[10];
    float* out = (float*)d_out;

    float *xn, *qp, *kp, *vp, *zp, *wt, *bqkv;
    cudaGetSymbolAddress((void**)&xn, g_xn);
    cudaGetSymbolAddress((void**)&qp, g_q);
    cudaGetSymbolAddress((void**)&kp, g_k);
    cudaGetSymbolAddress((void**)&vp, g_v);
    cudaGetSymbolAddress((void**)&zp, g_z);
    cudaGetSymbolAddress((void**)&wt, g_wt);
    cudaGetSymbolAddress((void**)&bqkv, g_bqkv);
    float* wqkv = wt;
    float* wo   = wt + 3 * DH * DH;

    cudaFuncSetAttribute(gemm_qkv_kernel,
                         cudaFuncAttributeMaxDynamicSharedMemorySize, GEMM_SMEM);
    cudaFuncSetAttribute(gemm_o_kernel,
                         cudaFuncAttributeMaxDynamicSharedMemorySize, GEMM_SMEM);
    cudaFuncSetAttribute(attn_kernel,
                         cudaFuncAttributeMaxDynamicSharedMemorySize, ATTN_SMEM);

    // 0. weights: tf32 + permute; biases: pack
    dim3 wgrid(DH * DH / 1024, 4);
    wcvt_kernel<<<wgrid, 256>>>(Wq, Wk, Wv, Wo, wt);
    bpack_kernel<<<DH / 256, 256>>>(bq, bk, bv, bqkv);

    // 1. LayerNorm (tf32 + permuted out)
    ln_kernel<<<MROWS / 8, 256>>>(x, gamma, beta, xn);

    // 2. fused QKV projection
    dim3 qkvgrid(3 * GN / 128, GM / 128);
    gemm_qkv_kernel<<<qkvgrid, 256, GEMM_SMEM>>>(xn, wqkv, bqkv, qp, kp, vp);

    // 3. causal multi-head attention
    dim3 agrid(SEQ / BQ, NH, NB);
    attn_kernel<<<agrid, 256, ATTN_SMEM>>>(qp, kp, vp, zp);

    // 4. output projection (standard-layout fp32 output)
    dim3 ogrid(GN / 128, GM / 128);
    gemm_o_kernel<<<ogrid, 256, GEMM_SMEM>>>(zp, wo, bo, out);
}

// round 10
// speedup vs baseline: 2.0852x; 1.0213x over previous
#include <cuda_runtime.h>
#include <cuda_bf16.h>
#include <math.h>
#include <stdint.h>

// Problem constants
#define NB   4
#define SEQ  2048
#define DH   1024
#define NH   16
#define HD   64
#define MROWS (NB*SEQ)          // 8192

#define GM MROWS
#define GN DH
#define GK DH

// ---------------- scratch (static device globals; no allocation) -------------
__device__ float g_xn[MROWS * DH];      // permuted cols
__device__ float g_q [MROWS * DH];      // permuted cols
__device__ float g_k [MROWS * DH];      // permuted cols
__device__ float g_v [MROWS * DH];      // TRANSPOSED: [NB][NH][HD][SEQ], y permuted
__device__ float g_z [MROWS * DH];      // permuted cols
__device__ float g_wt[4][DH * DH];      // tf32, permuted cols (q,k,v,o)
__device__ float g_bqkv[3 * DH];        // packed biases (logical order)

// ---------------------------- helpers -----------------------------------------
// per-8 column permutation: logical j -> position 2*(j&3) + (j>>2)
__device__ __forceinline__ int pi8(int j) { return ((j & 3) << 1) | (j >> 2); }

__device__ __forceinline__ float f_tf32(float x) {
    uint32_t r;
    asm("cvt.rna.tf32.f32 %0, %1;" : "=r"(r) : "f"(x));
    return __uint_as_float(r);
}

__device__ __forceinline__ void mma_tf32(float* c, const float* a, const float* b) {
    asm volatile(
        "mma.sync.aligned.m16n8k8.row.col.f32.tf32.tf32.f32 "
        "{%0,%1,%2,%3}, {%4,%5,%6,%7}, {%8,%9}, {%0,%1,%2,%3};\n"
        : "+f"(c[0]), "+f"(c[1]), "+f"(c[2]), "+f"(c[3])
        : "r"(__float_as_uint(a[0])), "r"(__float_as_uint(a[1])),
          "r"(__float_as_uint(a[2])), "r"(__float_as_uint(a[3])),
          "r"(__float_as_uint(b[0])), "r"(__float_as_uint(b[1])));
}

__device__ __forceinline__ void cp_async16(void* smem, const void* gmem) {
    uint32_t s = (uint32_t)__cvta_generic_to_shared(smem);
    asm volatile("cp.async.cg.shared.global [%0], [%1], 16;" :: "r"(s), "l"(gmem));
}
__device__ __forceinline__ void cp_commit() {
    asm volatile("cp.async.commit_group;");
}
template<int N>
__device__ __forceinline__ void cp_wait() {
    asm volatile("cp.async.wait_group %0;" :: "n"(N));
}

// ----------------- weight pre-round (tf32) + permute + bias pack ---------------
__global__ __launch_bounds__(256) void wcvt_kernel(
    const float* __restrict__ w0, const float* __restrict__ w1,
    const float* __restrict__ w2, const float* __restrict__ w3,
    float* __restrict__ dst)
{
    const float* srcs[4] = {w0, w1, w2, w3};
    const float* src = srcs[blockIdx.y];
    float* d = dst + (size_t)blockIdx.y * DH * DH;
    int i = (blockIdx.x * 256 + threadIdx.x) * 4;
    float4 v = *(const float4*)&src[i];
    int base = i & ~7;
    int j0 = i & 7;          // 0 or 4
    d[base + pi8(j0 + 0)] = f_tf32(v.x);
    d[base + pi8(j0 + 1)] = f_tf32(v.y);
    d[base + pi8(j0 + 2)] = f_tf32(v.z);
    d[base + pi8(j0 + 3)] = f_tf32(v.w);
}

__global__ __launch_bounds__(256) void bpack_kernel(
    const float* __restrict__ b0, const float* __restrict__ b1,
    const float* __restrict__ b2, float* __restrict__ dst)
{
    int i = blockIdx.x * 256 + threadIdx.x;
    dst[i]          = b0[i];
    dst[i + DH]     = b1[i];
    dst[i + 2 * DH] = b2[i];
}

// ---------------- LayerNorm (warp per row, tf32 + permuted out) ----------------
__global__ __launch_bounds__(256) void ln_kernel(
    const float* __restrict__ x, const float* __restrict__ gamma,
    const float* __restrict__ beta, float* __restrict__ xn)
{
    int warp = threadIdx.x >> 5, lane = threadIdx.x & 31;
    int row = blockIdx.x * 8 + warp;
    const float* xr = x + (size_t)row * DH;
    float* outr = xn + (size_t)row * DH;

    float4 v[8];
    float s = 0.f, sq = 0.f;
    #pragma unroll
    for (int j = 0; j < 8; j++) {
        v[j] = *(const float4*)&xr[(j * 32 + lane) * 4];
        s  += v[j].x + v[j].y + v[j].z + v[j].w;
        sq += v[j].x * v[j].x + v[j].y * v[j].y
            + v[j].z * v[j].z + v[j].w * v[j].w;
    }
    #pragma unroll
    for (int off = 16; off > 0; off >>= 1) {
        s  += __shfl_xor_sync(0xffffffffu, s,  off);
        sq += __shfl_xor_sync(0xffffffffu, sq, off);
    }
    float mu  = s * (1.0f / DH);
    float var = sq * (1.0f / DH) - mu * mu;
    float inv = rsqrtf(var + 1e-5f);

    #pragma unroll
    for (int j = 0; j < 8; j++) {
        int c = (j * 32 + lane) * 4;
        float4 g = *(const float4*)&gamma[c];
        float4 b = *(const float4*)&beta[c];
        int base = c & ~7;
        int j0 = c & 7;
        outr[base + pi8(j0 + 0)] = f_tf32((v[j].x - mu) * inv * g.x + b.x);
        outr[base + pi8(j0 + 1)] = f_tf32((v[j].y - mu) * inv * g.y + b.y);
        outr[base + pi8(j0 + 2)] = f_tf32((v[j].z - mu) * inv * g.z + b.z);
        outr[base + pi8(j0 + 3)] = f_tf32((v[j].w - mu) * inv * g.w + b.w);
    }
}

// ----------- GEMM core (tf32, cp.async 2-stage, ONE sync/iter) ----------------
#define SA 40
#define GTILE (128 * SA)
#define GEMM_SMEM (4 * GTILE * (int)sizeof(float))

struct GemmCore {
    float acc[4][4][4];
    int t, lane, wid, lr, lc, m_base, n_base;

    __device__ __forceinline__ void init(int tid) {
        t = tid; lane = t & 31; wid = t >> 5;
        lr = lane >> 2; lc = lane & 3;
        m_base = (wid & 1) * 64;
        n_base = (wid >> 1) * 32;
        #pragma unroll
        for (int i = 0; i < 4; i++)
            #pragma unroll
            for (int j = 0; j < 4; j++)
                #pragma unroll
                for (int e = 0; e < 4; e++) acc[i][j][e] = 0.f;
    }

    __device__ __forceinline__ void run(
        float* As, float* Bs,
        const float* __restrict__ A, const float* __restrict__ W, int m0)
    {
        // prologue: tile 0 into buf 0
        #pragma unroll
        for (int i = 0; i < 4; i++) {
            int e = t + i * 256;
            int row = e >> 3, c4 = (e & 7) * 4;
            cp_async16(&As[row * SA + c4], &A[(size_t)(m0 + row) * GK + c4]);
            cp_async16(&Bs[row * SA + c4], &W[(size_t)row * GK + c4]);
        }
        cp_commit();

        int buf = 0;
        for (int k0 = 0; k0 < GK; k0 += 32) {
            bool more = (k0 + 32 < GK);
            cp_wait<0>();      // tile i's group complete (only one outstanding)
            __syncthreads();   // visible to all; also: iter i-1 compute finished

            if (more) {
                float* Aw = &As[(buf ^ 1) * GTILE];
                float* Bw = &Bs[(buf ^ 1) * GTILE];
                #pragma unroll
                for (int i = 0; i < 4; i++) {
                    int e = t + i * 256;
                    int row = e >> 3, c4 = (e & 7) * 4;
                    cp_async16(&Aw[row * SA + c4],
                               &A[(size_t)(m0 + row) * GK + k0 + 32 + c4]);
                    cp_async16(&Bw[row * SA + c4],
                               &W[(size_t)row * GK + k0 + 32 + c4]);
                }
                cp_commit();
            }

            const float* Ab = &As[buf * GTILE];
            const float* Bb = &Bs[buf * GTILE];
            #pragma unroll
            for (int kk = 0; kk < 4; kk++) {
                int kb = kk * 8 + 2 * lc;
                float a[4][4], b[4][2];
                #pragma unroll
                for (int mf = 0; mf < 4; mf++) {
                    int row = m_base + mf * 16 + lr;
                    float2 lo = *(const float2*)&Ab[row * SA + kb];
                    float2 hi = *(const float2*)&Ab[(row + 8) * SA + kb];
                    a[mf][0] = lo.x; a[mf][1] = hi.x;
                    a[mf][2] = lo.y; a[mf][3] = hi.y;
                }
                #pragma unroll
                for (int nf = 0; nf < 4; nf++) {
                    int col = n_base + nf * 8 + lr;
                    float2 bb = *(const float2*)&Bb[col * SA + kb];
                    b[nf][0] = bb.x; b[nf][1] = bb.y;
                }
                #pragma unroll
                for (int mf = 0; mf < 4; mf++)
                    #pragma unroll
                    for (int nf = 0; nf < 4; nf++)
                        mma_tf32(acc[mf][nf], a[mf], b[nf]);
            }
            buf ^= 1;
        }
    }
};

// Fused QKV GEMM. Wp: [3072 x 1024] permuted-col. Writes q,k permuted-col;
// v transposed [NB][NH][HD][SEQ] with y permuted (for attention PV).
__global__ __launch_bounds__(256, 2) void gemm_qkv_kernel(
    const float* __restrict__ A, const float* __restrict__ Wp,
    const float* __restrict__ bp,
    float* __restrict__ q, float* __restrict__ k, float* __restrict__ v)
{
    extern __shared__ float gsm[];
    GemmCore core;
    core.init(threadIdx.x);

    int npack0 = blockIdx.x * 128;
    int m0 = blockIdx.y * 128;
    int mat = npack0 >> 10;               // 0=q 1=k 2=v
    int ncol0 = npack0 & 1023;

    core.run(gsm, gsm + 2 * GTILE, A, Wp + (size_t)npack0 * GK, m0);

    const float* bias = bp + npack0;
    int lr = core.lr, lc = core.lc;
    int p0 = pi8(2 * lc), p1 = pi8(2 * lc + 1);

    #pragma unroll
    for (int nf = 0; nf < 4; nf++) {
        int cb = core.n_base + nf * 8;
        float b0 = bias[cb + 2 * lc];
        float b1 = bias[cb + 2 * lc + 1];
        #pragma unroll
        for (int mf = 0; mf < 4; mf++) {
            int row = m0 + core.m_base + mf * 16 + lr;
            float v0 = f_tf32(core.acc[mf][nf][0] + b0);
            float v1 = f_tf32(core.acc[mf][nf][1] + b1);
            float v2 = f_tf32(core.acc[mf][nf][2] + b0);
            float v3 = f_tf32(core.acc[mf][nf][3] + b1);
            if (mat == 2) {
                int c0 = ncol0 + cb + 2 * lc;
                int yl = row & (SEQ - 1);
                int py = (yl & ~7) | pi8(yl & 7);
                size_t b_ = (size_t)(row >> 11) * DH;
                v[(b_ + c0)     * SEQ + py]     = v0;
                v[(b_ + c0 + 1) * SEQ + py]     = v1;
                v[(b_ + c0)     * SEQ + py + 8] = v2;
                v[(b_ + c0 + 1) * SEQ + py + 8] = v3;
            } else {
                float* C = (mat == 0) ? q : k;
                int colb = ncol0 + cb;
                C[(size_t)row * GN + colb + p0]       = v0;
                C[(size_t)row * GN + colb + p1]       = v1;
                C[(size_t)(row + 8) * GN + colb + p0] = v2;
                C[(size_t)(row + 8) * GN + colb + p1] = v3;
            }
        }
    }
}

// Output projection: A (z) permuted-col, W permuted-col, OUTPUT standard layout.
__global__ __launch_bounds__(256, 2) void gemm_o_kernel(
    const float* __restrict__ A, const float* __restrict__ W,
    const float* __restrict__ bias, float* __restrict__ C)
{
    extern __shared__ float gsm[];
    GemmCore core;
    core.init(threadIdx.x);
    int n0 = blockIdx.x * 128;
    int m0 = blockIdx.y * 128;
    core.run(gsm, gsm + 2 * GTILE, A, W + (size_t)n0 * GK, m0);

    int lr = core.lr, lc = core.lc;
    #pragma unroll
    for (int nf = 0; nf < 4; nf++) {
        int col = n0 + core.n_base + nf * 8 + 2 * lc;
        float b0 = bias[col], b1 = bias[col + 1];
        #pragma unroll
        for (int mf = 0; mf < 4; mf++) {
            int row = m0 + core.m_base + mf * 16 + lr;
            *(float2*)&C[(size_t)row * GN + col] =
                make_float2(core.acc[mf][nf][0] + b0, core.acc[mf][nf][1] + b1);
            *(float2*)&C[(size_t)(row + 8) * GN + col] =
                make_float2(core.acc[mf][nf][2] + b0, core.acc[mf][nf][3] + b1);
        }
    }
}

// ------ Flash Attention (tf32; Q in registers, double-buffered K/V) -----------
#define BQ  128
#define BKT 64
#define AST 72
#define KV_T (BKT * AST)
#define ATTN_SMEM ((4*KV_T + BQ*AST) * (int)sizeof(float))

__global__ __launch_bounds__(256, 2) void attn_kernel(
    const float* __restrict__ q, const float* __restrict__ k,
    const float* __restrict__ v, float* __restrict__ z)
{
    extern __shared__ float sm[];
    float* Ks = sm;                    // [2][64 y][AST] permuted d
    float* Vt = sm + 2 * KV_T;         // [2][64 d][AST] permuted y
    float* Ps = sm + 4 * KV_T;         // [128 r][AST]   permuted y (per-warp)

    int xc = (gridDim.x - 1) - blockIdx.x;   // heavy tiles first
    int h  = blockIdx.y;
    int n  = blockIdx.z;
    int x0 = xc * BQ;
    int t    = threadIdx.x;
    int lane = t & 31;
    int wid  = t >> 5;
    int lr = lane >> 2;
    int lc = lane & 3;
    int m_base = wid * 16;
    float* Pw = Ps + m_base * AST;
    int pp0 = pi8(2 * lc), pp1 = pi8(2 * lc + 1);

    const float* qb = q + ((size_t)n * SEQ) * DH + h * HD;
    const float* kb = k + ((size_t)n * SEQ) * DH + h * HD;
    const float* vtb = v + ((size_t)(n * NH + h) * HD) * SEQ;  // [64 d][2048 y]

    // prologue: K0/V0 via cp.async (one group per tile)
    #pragma unroll
    for (int i = 0; i < 4; i++) {
        int f = t + i * 256;
        int r = f >> 4, c4 = (f & 15) * 4;
        cp_async16(&Ks[r * AST + c4], &kb[(size_t)r * DH + c4]);
        cp_async16(&Vt[r * AST + c4], &vtb[(size_t)r * SEQ + c4]);
    }
    cp_commit();

    // Q fragments in registers for the whole kernel (1/8 scale folded in —
    // exact pow2, commutes bit-exactly through the fp32 mma chain)
    float qa[8][4];
    #pragma unroll
    for (int kk = 0; kk < 8; kk++) {
        float2 lo = *(const float2*)&qb[(size_t)(x0 + m_base + lr) * DH + kk * 8 + 2 * lc];
        float2 hi = *(const float2*)&qb[(size_t)(x0 + m_base + lr + 8) * DH + kk * 8 + 2 * lc];
        qa[kk][0] = lo.x * 0.125f; qa[kk][1] = hi.x * 0.125f;
        qa[kk][2] = lo.y * 0.125f; qa[kk][3] = hi.y * 0.125f;
    }

    float m_lo = -INFINITY, m_hi = -INFINITY, l_lo = 0.f, l_hi = 0.f;
    float o[8][4];
    #pragma unroll
    for (int nf = 0; nf < 8; nf++)
        #pragma unroll
        for (int e = 0; e < 4; e++) o[nf][e] = 0.f;

    int yend = x0 + BQ;
    int buf = 0;
    for (int y0 = 0; y0 < yend; y0 += BKT) {
        bool more = (y0 + BKT < yend);
        if (more) {
            // prefetch tile i+1 into buf^1 (its readers finished before the
            // previous end-of-iter barrier)
            float* Kw = &Ks[(buf ^ 1) * KV_T];
            float* Vw = &Vt[(buf ^ 1) * KV_T];
            #pragma unroll
            for (int i = 0; i < 4; i++) {
                int f = t + i * 256;
                int r = f >> 4, c4 = (f & 15) * 4;
                cp_async16(&Kw[r * AST + c4],
                           &kb[(size_t)(y0 + BKT + r) * DH + c4]);
                cp_async16(&Vw[r * AST + c4],
                           &vtb[(size_t)r * SEQ + y0 + BKT + c4]);
            }
            cp_commit();
            cp_wait<1>();      // tile i's group complete; i+1 in flight
        } else {
            cp_wait<0>();
        }
        __syncthreads();       // tile i data visible to all warps

        const float* Kb = &Ks[buf * KV_T];
        const float* Vb = &Vt[buf * KV_T];

        // ---- S = Q K^T (Q from registers) ----
        float s[8][4];
        #pragma unroll
        for (int nf = 0; nf < 8; nf++)
            #pragma unroll
            for (int e = 0; e < 4; e++) s[nf][e] = 0.f;

        #pragma unroll
        for (int kk = 0; kk < 8; kk++) {
            int kb8 = kk * 8 + 2 * lc;
            #pragma unroll
            for (int nf = 0; nf < 8; nf++) {
                float2 kk2 = *(const float2*)&Kb[(nf * 8 + lr) * AST + kb8];
                float b[2] = {kk2.x, kk2.y};
                mma_tf32(s[nf], qa[kk], b);
            }
        }

        // ---- causal mask (logical y cols; straddling tiles only) ----
        if (y0 + BKT - 1 > x0) {
            int r_lo = x0 + m_base + lr;
            #pragma unroll
            for (int nf = 0; nf < 8; nf++) {
                int c = y0 + nf * 8 + 2 * lc;
                if (c     > r_lo) s[nf][0] = -INFINITY;
                if (c + 1 > r_lo) s[nf][1] = -INFINITY;
                if (c     > r_lo + 8) s[nf][2] = -INFINITY;
                if (c + 1 > r_lo + 8) s[nf][3] = -INFINITY;
            }
        }

        // ---- online softmax (4-lane row groups) ----
        float mt_lo = -INFINITY, mt_hi = -INFINITY;
        #pragma unroll
        for (int nf = 0; nf < 8; nf++) {
            mt_lo = fmaxf(mt_lo, fmaxf(s[nf][0], s[nf][1]));
            mt_hi = fmaxf(mt_hi, fmaxf(s[nf][2], s[nf][3]));
        }
        #pragma unroll
        for (int off = 1; off <= 2; off <<= 1) {
            mt_lo = fmaxf(mt_lo, __shfl_xor_sync(0xffffffffu, mt_lo, off));
            mt_hi = fmaxf(mt_hi, __shfl_xor_sync(0xffffffffu, mt_hi, off));
        }
        float mn_lo = fmaxf(m_lo, mt_lo);
        float mn_hi = fmaxf(m_hi, mt_hi);
        float al_lo = __expf(m_lo - mn_lo);
        float al_hi = __expf(m_hi - mn_hi);
        m_lo = mn_lo; m_hi = mn_hi;

        float rs_lo = 0.f, rs_hi = 0.f;
        #pragma unroll
        for (int nf = 0; nf < 8; nf++) {
            s[nf][0] = __expf(s[nf][0] - mn_lo);
            s[nf][1] = __expf(s[nf][1] - mn_lo);
            s[nf][2] = __expf(s[nf][2] - mn_hi);
            s[nf][3] = __expf(s[nf][3] - mn_hi);
            rs_lo += s[nf][0] + s[nf][1];
            rs_hi += s[nf][2] + s[nf][3];
        }
        #pragma unroll
        for (int off = 1; off <= 2; off <<= 1) {
            rs_lo += __shfl_xor_sync(0xffffffffu, rs_lo, off);
            rs_hi += __shfl_xor_sync(0xffffffffu, rs_hi, off);
        }
        l_lo = l_lo * al_lo + rs_lo;
        l_hi = l_hi * al_hi + rs_hi;
        #pragma unroll
        for (int nf = 0; nf < 8; nf++) {
            o[nf][0] *= al_lo; o[nf][1] *= al_lo;
            o[nf][2] *= al_hi; o[nf][3] *= al_hi;
        }

        // ---- stage P (warp-private; y permuted per-8, tf32) ----
        #pragma unroll
        for (int nf = 0; nf < 8; nf++) {
            int q0 = nf * 8 + pp0;
            int q1 = nf * 8 + pp1;
            Pw[lr * AST + q0]       = f_tf32(s[nf][0]);
            Pw[lr * AST + q1]       = f_tf32(s[nf][1]);
            Pw[(lr + 8) * AST + q0] = f_tf32(s[nf][2]);
            Pw[(lr + 8) * AST + q1] = f_tf32(s[nf][3]);
        }
        __syncwarp();

        // ---- O += P V ----
        #pragma unroll
        for (int kk = 0; kk < 8; kk++) {
            int kb8 = kk * 8 + 2 * lc;
            float2 plo = *(const float2*)&Pw[lr * AST + kb8];
            float2 phi = *(const float2*)&Pw[(lr + 8) * AST + kb8];
            float a[4] = {plo.x, phi.x, plo.y, phi.y};
            #pragma unroll
            for (int nf = 0; nf < 8; nf++) {
                float2 vv = *(const float2*)&Vb[(nf * 8 + lr) * AST + kb8];
                float b[2] = {vv.x, vv.y};
                mma_tf32(o[nf], a, b);
            }
        }
        __syncwarp();
        __syncthreads();       // all warps done reading buf before it's refilled
        buf ^= 1;
    }

    // ---- normalize + store (permuted d cols, tf32: feeds o-proj) ----
    float inv_lo = 1.0f / l_lo;
    float inv_hi = 1.0f / l_hi;
    int r_lo = x0 + m_base + lr;
    #pragma unroll
    for (int nf = 0; nf < 8; nf++) {
        int dbase = h * HD + nf * 8;
        float* zlo = &z[((size_t)n * SEQ + r_lo) * DH + dbase];
        float* zhi = &z[((size_t)n * SEQ + r_lo + 8) * DH + dbase];
        zlo[pp0] = f_tf32(o[nf][0] * inv_lo);
        zlo[pp1] = f_tf32(o[nf][1] * inv_lo);
        zhi[pp0] = f_tf32(o[nf][2] * inv_hi);
        zhi[pp1] = f_tf32(o[nf][3] * inv_hi);
    }
}

// ------------------------------ launcher --------------------------------------
extern "C" void kernel_launch(void* const* d_in, const int* in_sizes, int n_in,
                              void* d_out, int out_size)
{
    const float* x     = (const float*)d_in[0];
    const float* Wq    = (const float*)d_in[1];
    const float* bq    = (const float*)d_in[2];
    const float* Wk    = (const float*)d_in[3];
    const float* bk    = (const float*)d_in[4];
    const float* Wv    = (const float*)d_in[5];
    const float* bv    = (const float*)d_in[6];
    const float* Wo    = (const float*)d_in[7];
    const float* bo    = (const float*)d_in[8];
    const float* gamma = (const float*)d_in[9];
    const float* beta  = (const float*)d_in[10];
    float* out = (float*)d_out;

    float *xn, *qp, *kp, *vp, *zp, *wt, *bqkv;
    cudaGetSymbolAddress((void**)&xn, g_xn);
    cudaGetSymbolAddress((void**)&qp, g_q);
    cudaGetSymbolAddress((void**)&kp, g_k);
    cudaGetSymbolAddress((void**)&vp, g_v);
    cudaGetSymbolAddress((void**)&zp, g_z);
    cudaGetSymbolAddress((void**)&wt, g_wt);
    cudaGetSymbolAddress((void**)&bqkv, g_bqkv);
    float* wqkv = wt;
    float* wo   = wt + 3 * DH * DH;

    cudaFuncSetAttribute(gemm_qkv_kernel,
                         cudaFuncAttributeMaxDynamicSharedMemorySize, GEMM_SMEM);
    cudaFuncSetAttribute(gemm_o_kernel,
                         cudaFuncAttributeMaxDynamicSharedMemorySize, GEMM_SMEM);
    cudaFuncSetAttribute(attn_kernel,
                         cudaFuncAttributeMaxDynamicSharedMemorySize, ATTN_SMEM);

    // 0. weights: tf32 + permute; biases: pack
    dim3 wgrid(DH * DH / 1024, 4);
    wcvt_kernel<<<wgrid, 256>>>(Wq, Wk, Wv, Wo, wt);
    bpack_kernel<<<DH / 256, 256>>>(bq, bk, bv, bqkv);

    // 1. LayerNorm (tf32 + permuted out)
    ln_kernel<<<MROWS / 8, 256>>>(x, gamma, beta, xn);

    // 2. fused QKV projection
    dim3 qkvgrid(3 * GN / 128, GM / 128);
    gemm_qkv_kernel<<<qkvgrid, 256, GEMM_SMEM>>>(xn, wqkv, bqkv, qp, kp, vp);

    // 3. causal multi-head attention
    dim3 agrid(SEQ / BQ, NH, NB);
    attn_kernel<<<agrid, 256, ATTN_SMEM>>>(qp, kp, vp, zp);

    // 4. output projection (standard-layout fp32 output)
    dim3 ogrid(GN / 128, GM / 128);
    gemm_o_kernel<<<ogrid, 256, GEMM_SMEM>>>(zp, wo, bo, out);
}